// round 7
// baseline (speedup 1.0000x reference)
#include <cuda_runtime.h>
#include <cstdint>

// ------------------------- problem dims -------------------------
#define B_ 32
#define T_ 100
#define V_ 20000
#define E_ 128
#define H_ 128
#define M_ 64
#define ROWS_X (B_*T_)          // 3200
#define ROWS_TOT (ROWS_X + B_)  // 3232

// ------------------------- k1 config ----------------------------
#define CK 128                  // k per chunk (128 int8 = 128B rows, SW128)
#define NCH 157                 // ceil(20000/128)
#define NRT 26                  // row tiles of 128
#define NSPL 17                 // K splits
#define BASECH 9                // 157 = 4*10 + 13*9
#define EXTRA 4
#define GRID1 (NRT*NSPL)        // 442

// quantization scales: x: q=round(v*32512) (v in [0,1]); emb: q=round(v*325120)
#define SA_ 32512.0f
#define SB_ 325120.0f

// smem: AH[2][16K] AL[2][16K] BH[2][16K] BL[2][16K]
#define OFF_AH 0
#define OFF_AL 32768
#define OFF_BH 65536
#define OFF_BL 98304
#define SMEM_K1 131072

// k3 dynamic smem layout (floats)
#define K3_XP   0                    // [100*384]
#define K3_RP   (K3_XP + T_*384)     // [384]
#define K3_H    (K3_RP + 384)        // [128]
#define K3_MSK  (K3_H + 128)         // [100]
#define K3_CS   (K3_MSK + 100)       // [64]
#define SMEM_K3 ((K3_CS + 64 + 4) * 4)   // ~156.4 KB

// ------------------------- scratch globals ----------------------
__device__ float    g_parts[(size_t)NSPL * ROWS_TOT * 128];  // 28.1 MB
__device__ uint32_t g_ebh[(size_t)NCH * 4096];               // emb hi int8, tile-swizzled
__device__ uint32_t g_ebl[(size_t)NCH * 4096];               // emb lo int8
__device__ float    g_P[(size_t)ROWS_X * 384];
__device__ float    g_mask[ROWS_X];
__device__ float    g_ae[B_ * E_];

// ------------------------- helpers ------------------------------
__device__ __forceinline__ unsigned su32(const void* p) {
    return (unsigned)__cvta_generic_to_shared(p);
}
__device__ __forceinline__ void cpa16(unsigned dst, const void* src) {
    asm volatile("cp.async.ca.shared.global [%0], [%1], 16;\n"
                 :: "r"(dst), "l"(src));
}
__device__ __forceinline__ void ldsm4(uint32_t* r, uint32_t addr) {
    asm volatile("ldmatrix.sync.aligned.m8n8.x4.shared.b16 {%0,%1,%2,%3}, [%4];"
                 : "=r"(r[0]), "=r"(r[1]), "=r"(r[2]), "=r"(r[3]) : "r"(addr));
}
__device__ __forceinline__ void imma(int* c, const uint32_t* a, const uint32_t* b) {
    asm volatile("mma.sync.aligned.m16n8k32.row.col.s32.s8.s8.s32 "
                 "{%0,%1,%2,%3}, {%4,%5,%6,%7}, {%8,%9}, {%0,%1,%2,%3};"
                 : "+r"(c[0]), "+r"(c[1]), "+r"(c[2]), "+r"(c[3])
                 : "r"(a[0]), "r"(a[1]), "r"(a[2]), "r"(a[3]), "r"(b[0]), "r"(b[1]));
}
// quantize 4 floats (pre-scaled ints) -> hi/lo packed bytes
__device__ __forceinline__ void quant4(float4 v, float scale, uint32_t& hw, uint32_t& lw) {
    int i0 = __float2int_rn(v.x * scale);
    int i1 = __float2int_rn(v.y * scale);
    int i2 = __float2int_rn(v.z * scale);
    int i3 = __float2int_rn(v.w * scale);
    int h0 = (i0 + 128) >> 8, h1 = (i1 + 128) >> 8;
    int h2 = (i2 + 128) >> 8, h3 = (i3 + 128) >> 8;
    int l0 = i0 - (h0 << 8), l1 = i1 - (h1 << 8);
    int l2 = i2 - (h2 << 8), l3 = i3 - (h3 << 8);
    hw = (h0 & 255) | ((h1 & 255) << 8) | ((h2 & 255) << 16) | ((h3 & 255) << 24);
    lw = (l0 & 255) | ((l1 & 255) << 8) | ((l2 & 255) << 16) | ((l3 & 255) << 24);
}

// fast transcendentals (MUFU-based, err ~2^-22)
#define LOG2E_ 1.4426950408889634f
__device__ __forceinline__ float ex2f(float x) {
    float r; asm("ex2.approx.f32 %0, %1;" : "=f"(r) : "f"(x)); return r;
}
__device__ __forceinline__ float rcpf(float x) {
    float r; asm("rcp.approx.f32 %0, %1;" : "=f"(r) : "f"(x)); return r;
}
__device__ __forceinline__ float sigmoid_f(float v) {
    return rcpf(1.f + ex2f(-v * LOG2E_));
}
__device__ __forceinline__ float tanh_f(float v) {
    return 1.f - 2.f * rcpf(ex2f(2.f * LOG2E_ * v) + 1.f);
}

// ---------------------------------------------------------------------------
// Kernel 0: emb -> transposed, int8 hi/lo split, SW128-swizzled 16KB tiles.
// Tile c: [n=0..127 rows][k=0..127 int8], 128B rows. One CTA per chunk,
// processed in two k-halves of 64 (smem budget).
// ---------------------------------------------------------------------------
__global__ void __launch_bounds__(256) k0_prep(const float* __restrict__ emb)
{
    __shared__ float se[64][129];   // [kl][n]
    const int c = blockIdx.x, tid = threadIdx.x;
    uint32_t* oh = g_ebh + (size_t)c * 4096;
    uint32_t* ol = g_ebl + (size_t)c * 4096;

    for (int h = 0; h < 2; h++) {
        for (int i = tid; i < 64 * 128; i += 256) {
            int kl = i >> 7, r = i & 127;
            int k = c * CK + h * 64 + kl;
            se[kl][r] = (k < V_) ? emb[(size_t)k * E_ + r] : 0.f;
        }
        __syncthreads();

        for (int w = tid; w < 4096; w += 256) {
            uint32_t sw = 4u * w;
            int r = sw >> 7;
            int kb = (int)((sw & 127u) ^ ((uint32_t)(r & 7) << 4));
            if ((kb >> 6) == h) {
                int kl = kb & 63;
                float4 v = make_float4(se[kl][r], se[kl + 1][r],
                                       se[kl + 2][r], se[kl + 3][r]);
                uint32_t hw, lw;
                quant4(v, SB_, hw, lw);
                oh[w] = hw;
                ol[w] = lw;
            }
        }
        __syncthreads();
    }
}

// ---------------------------------------------------------------------------
// Kernel 1: 16-bit fixed-point GEMM via int8 IMMA (3 terms), split-K partials.
// sum = (65536*D + 256*E) / (SA*SB), D=ΣAhBh, E=Σ(AhBl+AlBh), ll dropped.
// ---------------------------------------------------------------------------
__global__ void __launch_bounds__(512, 1) k1_gemm(
    const float* __restrict__ x, const float* __restrict__ a_)
{
    extern __shared__ char smem[];
    const uint32_t sb = su32(smem);
    const int tid = threadIdx.x;
    const int lane = tid & 31;
    const int wid = tid >> 5;
    const int wm = wid >> 2;
    const int wn = wid & 3;

    const int rt = blockIdx.x % NRT;
    const int sp = blockIdx.x / NRT;
    const int m0 = rt * 128;
    const int nch = BASECH + (sp < EXTRA ? 1 : 0);
    const int c0  = sp * BASECH + (sp < EXTRA ? sp : EXTRA);

    const int arow = tid >> 2;          // 0..127
    const int aseg = tid & 3;           // k segment of 32 floats
    const uint32_t xs_a = (uint32_t)(arow & 7) << 4;

    const float* rowp;
    {
        int m = m0 + arow;
        if (m < ROWS_X)        rowp = x  + (size_t)m * V_;
        else if (m < ROWS_TOT) rowp = a_ + (size_t)(m - ROWS_X) * V_;
        else                   rowp = nullptr;
    }

    const int aq = lane >> 3;
    const int a_row_off = (aq & 1) * 8 + (lane & 7);
    const uint32_t a_kboff = (uint32_t)(aq >> 1) * 16;
    const uint32_t abase0 = (uint32_t)(wm * 32 + 0 * 16 + a_row_off) * 128;
    const uint32_t abase1 = (uint32_t)(wm * 32 + 1 * 16 + a_row_off) * 128;
    const int bjj = lane >> 4;
    const uint32_t b_kboff = (uint32_t)((lane >> 3) & 1) * 16;
    const uint32_t bbase0 = (uint32_t)(wn * 32 + 0 * 16 + bjj * 8 + (lane & 7)) * 128;
    const uint32_t bbase1 = (uint32_t)(wn * 32 + 1 * 16 + bjj * 8 + (lane & 7)) * 128;
    const uint32_t xorv = (uint32_t)(lane & 7) << 4;

    int accD[2][4][4], accE[2][4][4];
    #pragma unroll
    for (int i = 0; i < 2; i++)
        #pragma unroll
        for (int j = 0; j < 4; j++)
            #pragma unroll
            for (int q = 0; q < 4; q++) { accD[i][j][q] = 0; accE[i][j][q] = 0; }

    float4 av[8];   // 32 floats: k = aseg*32 + q*4

    auto loadA = [&](int c) {
        #pragma unroll
        for (int q = 0; q < 8; q++) {
            int kb = c * CK + aseg * 32 + q * 4;
            av[q] = (rowp && kb < V_) ? *(const float4*)(rowp + kb)
                                      : make_float4(0.f, 0.f, 0.f, 0.f);
        }
    };
    // quantize av -> int8 hi/lo, swizzled STS (STS.64 over 8-k units)
    auto stsA = [&](int s) {
        const uint32_t ah = sb + OFF_AH + s * 16384 + arow * 128;
        const uint32_t al = sb + OFF_AL + s * 16384 + arow * 128;
        #pragma unroll
        for (int m = 0; m < 4; m++) {
            uint32_t H0, H1, L0, L1;
            quant4(av[2 * m],     SA_, H0, L0);
            quant4(av[2 * m + 1], SA_, H1, L1);
            uint32_t k = (uint32_t)(aseg * 32 + m * 8);
            uint32_t off = k ^ xs_a;
            asm volatile("st.shared.v2.b32 [%0], {%1,%2};" :: "r"(ah + off), "r"(H0), "r"(H1));
            asm volatile("st.shared.v2.b32 [%0], {%1,%2};" :: "r"(al + off), "r"(L0), "r"(L1));
        }
    };
    auto cpB = [&](int c, int s) {
        const char* srcH = (const char*)g_ebh + (size_t)c * 16384;
        const char* srcL = (const char*)g_ebl + (size_t)c * 16384;
        const uint32_t bh = sb + OFF_BH + s * 16384;
        const uint32_t bl = sb + OFF_BL + s * 16384;
        #pragma unroll
        for (int j = 0; j < 2; j++) {
            int off = (j * 512 + tid) * 16;
            cpa16(bh + off, srcH + off);
            cpa16(bl + off, srcL + off);
        }
        asm volatile("cp.async.commit_group;");
    };

    loadA(c0);
    stsA(0);
    cpB(c0, 0);
    if (nch > 1) loadA(c0 + 1);

    for (int t = 0; t < nch; t++) {
        const int s = t & 1;
        asm volatile("cp.async.wait_group 0;" ::: "memory");
        __syncthreads();

        if (t + 1 < nch) {
            cpB(c0 + t + 1, s ^ 1);
            stsA(s ^ 1);
            if (t + 2 < nch) loadA(c0 + t + 2);
        }

        const uint32_t ahs = sb + OFF_AH + s * 16384;
        const uint32_t als = sb + OFF_AL + s * 16384;
        const uint32_t bhs = sb + OFF_BH + s * 16384;
        const uint32_t bls = sb + OFF_BL + s * 16384;

        #pragma unroll
        for (int ks = 0; ks < 4; ks++) {
            const uint32_t kta = ((uint32_t)(ks * 32) + a_kboff) ^ xorv;
            const uint32_t ktb = ((uint32_t)(ks * 32) + b_kboff) ^ xorv;
            uint32_t ah0[4], ah1[4], al0[4], al1[4], bh[2][4], bl[2][4];
            ldsm4(ah0, ahs + abase0 + kta);
            ldsm4(ah1, ahs + abase1 + kta);
            ldsm4(al0, als + abase0 + kta);
            ldsm4(al1, als + abase1 + kta);
            ldsm4(bh[0], bhs + bbase0 + ktb);
            ldsm4(bh[1], bhs + bbase1 + ktb);
            ldsm4(bl[0], bls + bbase0 + ktb);
            ldsm4(bl[1], bls + bbase1 + ktb);
            #pragma unroll
            for (int j = 0; j < 4; j++) {
                const uint32_t* bhp = &bh[j >> 1][(j & 1) * 2];
                const uint32_t* blp = &bl[j >> 1][(j & 1) * 2];
                imma(accD[0][j], ah0, bhp);
                imma(accD[1][j], ah1, bhp);
                imma(accE[0][j], ah0, blp);
                imma(accE[1][j], ah1, blp);
                imma(accE[0][j], al0, bhp);
                imma(accE[1][j], al1, bhp);
            }
        }
    }

    // epilogue: dequantize + write this split's partial tile
    const float INVQ = 1.0f / (SA_ * SB_);
    const int gid = lane >> 2, tig = lane & 3;
    #pragma unroll
    for (int i = 0; i < 2; i++) {
        int mrow = m0 + wm * 32 + i * 16 + gid;
        #pragma unroll
        for (int j = 0; j < 4; j++) {
            int n = wn * 32 + j * 8 + tig * 2;
            float v0 = fmaf((float)accD[i][j][0], 65536.f, (float)accE[i][j][0] * 256.f) * INVQ;
            float v1 = fmaf((float)accD[i][j][1], 65536.f, (float)accE[i][j][1] * 256.f) * INVQ;
            float v2 = fmaf((float)accD[i][j][2], 65536.f, (float)accE[i][j][2] * 256.f) * INVQ;
            float v3 = fmaf((float)accD[i][j][3], 65536.f, (float)accE[i][j][3] * 256.f) * INVQ;
            if (mrow < ROWS_TOT) {
                float* d0 = g_parts + ((size_t)sp * ROWS_TOT + mrow) * 128 + n;
                *(float2*)d0 = make_float2(v0, v1);
            }
            if (mrow + 8 < ROWS_TOT) {
                float* d1 = g_parts + ((size_t)sp * ROWS_TOT + mrow + 8) * 128 + n;
                *(float2*)d1 = make_float2(v2, v3);
            }
        }
    }
}

// ---------------------------------------------------------------------------
// Kernel 2: reduce partials + tanh -> xe; mask; x_proj = xe@gru_k + b_i.
// ---------------------------------------------------------------------------
__global__ void __launch_bounds__(128) k2_reduce_proj(
    const float* __restrict__ gk, const float* __restrict__ gbi)
{
    __shared__ float xs[16][128];
    __shared__ int nz[16];
    const int tid = threadIdx.x;
    const int r0 = blockIdx.x * 16;

    if (tid < 16) nz[tid] = 0;
    __syncthreads();

    for (int i = tid; i < 16 * 128; i += 128) {
        int r = i >> 7, n = i & 127;
        int m = r0 + r;
        float s = 0.f;
        const float* pp = g_parts + (size_t)m * 128 + n;
        #pragma unroll
        for (int sp = 0; sp < NSPL; sp++) s += pp[(size_t)sp * ROWS_TOT * 128];
        float v = tanh_f(s);
        xs[r][n] = v;
        if (v != 0.f) nz[r] = 1;
    }
    __syncthreads();

    if (r0 < ROWS_X) {
        float acc[16][3];
        #pragma unroll
        for (int r = 0; r < 16; r++) { acc[r][0] = 0.f; acc[r][1] = 0.f; acc[r][2] = 0.f; }
        for (int k = 0; k < 128; k++) {
            float w0 = gk[k * 384 + tid];
            float w1 = gk[k * 384 + 128 + tid];
            float w2 = gk[k * 384 + 256 + tid];
            #pragma unroll
            for (int r = 0; r < 16; r++) {
                float xv = xs[r][k];
                acc[r][0] = fmaf(xv, w0, acc[r][0]);
                acc[r][1] = fmaf(xv, w1, acc[r][1]);
                acc[r][2] = fmaf(xv, w2, acc[r][2]);
            }
        }
        float bb0 = gbi[tid], bb1 = gbi[128 + tid], bb2 = gbi[256 + tid];
        #pragma unroll
        for (int r = 0; r < 16; r++) {
            size_t m = (size_t)(r0 + r);
            g_P[m * 384 + tid]       = acc[r][0] + bb0;
            g_P[m * 384 + 128 + tid] = acc[r][1] + bb1;
            g_P[m * 384 + 256 + tid] = acc[r][2] + bb2;
        }
        if (tid < 16) g_mask[r0 + tid] = nz[tid] ? 1.f : 0.f;
    } else {
        for (int i = tid; i < 16 * 128; i += 128) {
            int r = i >> 7, n = i & 127;
            g_ae[(r0 - ROWS_X + r) * 128 + n] = xs[r][n];
        }
    }
}

// ---------------------------------------------------------------------------
// Kernel 3: per-batch GRU + head. 32 CTAs x 384 threads. x_proj + masks fully
// resident in dynamic smem; zero global traffic inside the recurrence loop.
// ---------------------------------------------------------------------------
__global__ void __launch_bounds__(384, 1) k3_gru(
    const float* __restrict__ grk, const float* __restrict__ gbr,
    const float* __restrict__ dvec, const float* __restrict__ W1,
    const float* __restrict__ b1, const float* __restrict__ W2,
    const float* __restrict__ b2, float* __restrict__ out)
{
    extern __shared__ float sm3[];
    float* xp  = sm3 + K3_XP;
    float* rp  = sm3 + K3_RP;
    float* h_s = sm3 + K3_H;
    float* msk = sm3 + K3_MSK;
    float* cs  = sm3 + K3_CS;

    const int tid = threadIdx.x;
    const int b = blockIdx.x;

    {
        const float* src = g_P + (size_t)b * T_ * 384;
        #pragma unroll
        for (int it = 0; it < 25; it++) {
            int i = it * 1536 + tid * 4;
            cpa16(su32(xp + i), src + i);
        }
        if (tid < 25) cpa16(su32(msk + tid * 4), g_mask + b * T_ + tid * 4);
        asm volatile("cp.async.commit_group;");
    }

    unsigned long long w2[64];
    #pragma unroll
    for (int q = 0; q < 64; q++) {
        float w0 = grk[(2 * q)     * 384 + tid];
        float w1 = grk[(2 * q + 1) * 384 + tid];
        asm("mov.b64 %0, {%1, %2};" : "=l"(w2[q]) : "f"(w0), "f"(w1));
    }
    const float bias = gbr[tid];

    if (tid < 128) h_s[tid] = 0.f;
    asm volatile("cp.async.wait_group 0;" ::: "memory");
    __syncthreads();

    for (int t = 0; t < T_; t++) {
        unsigned long long a0 = 0ULL, a1 = 0ULL, a2 = 0ULL, a3 = 0ULL;
        #pragma unroll
        for (int q = 0; q < 8; q++) {
            ulonglong2 u0 = *(const ulonglong2*)&h_s[q * 4];
            ulonglong2 u1 = *(const ulonglong2*)&h_s[32 + q * 4];
            ulonglong2 u2 = *(const ulonglong2*)&h_s[64 + q * 4];
            ulonglong2 u3 = *(const ulonglong2*)&h_s[96 + q * 4];
            asm("fma.rn.f32x2 %0, %1, %2, %0;" : "+l"(a0) : "l"(u0.x), "l"(w2[2 * q]));
            asm("fma.rn.f32x2 %0, %1, %2, %0;" : "+l"(a1) : "l"(u1.x), "l"(w2[16 + 2 * q]));
            asm("fma.rn.f32x2 %0, %1, %2, %0;" : "+l"(a2) : "l"(u2.x), "l"(w2[32 + 2 * q]));
            asm("fma.rn.f32x2 %0, %1, %2, %0;" : "+l"(a3) : "l"(u3.x), "l"(w2[48 + 2 * q]));
            asm("fma.rn.f32x2 %0, %1, %2, %0;" : "+l"(a0) : "l"(u0.y), "l"(w2[2 * q + 1]));
            asm("fma.rn.f32x2 %0, %1, %2, %0;" : "+l"(a1) : "l"(u1.y), "l"(w2[16 + 2 * q + 1]));
            asm("fma.rn.f32x2 %0, %1, %2, %0;" : "+l"(a2) : "l"(u2.y), "l"(w2[32 + 2 * q + 1]));
            asm("fma.rn.f32x2 %0, %1, %2, %0;" : "+l"(a3) : "l"(u3.y), "l"(w2[48 + 2 * q + 1]));
        }
        float s0, s1, s2, s3, s4, s5, s6, s7;
        asm("mov.b64 {%0, %1}, %2;" : "=f"(s0), "=f"(s1) : "l"(a0));
        asm("mov.b64 {%0, %1}, %2;" : "=f"(s2), "=f"(s3) : "l"(a1));
        asm("mov.b64 {%0, %1}, %2;" : "=f"(s4), "=f"(s5) : "l"(a2));
        asm("mov.b64 {%0, %1}, %2;" : "=f"(s6), "=f"(s7) : "l"(a3));
        rp[tid] = ((s0 + s1) + (s2 + s3)) + ((s4 + s5) + (s6 + s7)) + bias;
        __syncthreads();

        if (tid < 128) {
            const float* xpc = xp + t * 384;
            float z  = sigmoid_f(xpc[tid] + rp[tid]);
            float r  = sigmoid_f(xpc[tid + 128] + rp[tid + 128]);
            float hh = tanh_f(xpc[tid + 256] + r * rp[tid + 256]);
            float hprev = h_s[tid];
            float hn = z * hprev + (1.f - z) * hh;
            h_s[tid] = (msk[t] != 0.f) ? hn : hprev;
        }
        __syncthreads();
    }

    if (tid < 64) {
        float acc = b1[tid];
        const float* ae = g_ae + b * 128;
        #pragma unroll 4
        for (int k = 0; k < 128; k++) acc = fmaf(h_s[k], W1[k * 64 + tid], acc);
        #pragma unroll 4
        for (int k = 0; k < 128; k++) acc = fmaf(ae[k], W1[(128 + k) * 64 + tid], acc);
        cs[tid] = tanh_f(acc) * W2[tid];
    }
    __syncthreads();
    if (tid == 0) {
        float s = 0.f;
        #pragma unroll 8
        for (int i = 0; i < 64; i++) s += cs[i];
        s += dvec[b * 2] * W2[64] + dvec[b * 2 + 1] * W2[65] + b2[0];
        out[b] = sigmoid_f(s);
    }
}

// ---------------------------------------------------------------------------
extern "C" void kernel_launch(void* const* d_in, const int* in_sizes, int n_in,
                              void* d_out, int out_size)
{
    const float* x   = (const float*)d_in[0];
    const float* a   = (const float*)d_in[1];
    const float* dv  = (const float*)d_in[2];
    const float* emb = (const float*)d_in[3];
    const float* gk  = (const float*)d_in[4];
    const float* grk = (const float*)d_in[5];
    const float* gbi = (const float*)d_in[6];
    const float* gbr = (const float*)d_in[7];
    const float* W1  = (const float*)d_in[8];
    const float* b1  = (const float*)d_in[9];
    const float* W2  = (const float*)d_in[10];
    const float* b2  = (const float*)d_in[11];
    float* out = (float*)d_out;

    cudaFuncSetAttribute(k1_gemm, cudaFuncAttributeMaxDynamicSharedMemorySize, SMEM_K1);
    cudaFuncSetAttribute(k3_gru,  cudaFuncAttributeMaxDynamicSharedMemorySize, SMEM_K3);

    k0_prep<<<NCH, 256>>>(emb);
    k1_gemm<<<GRID1, 512, SMEM_K1>>>(x, a);
    k2_reduce_proj<<<ROWS_TOT / 16, 128>>>(gk, gbi);
    k3_gru<<<B_, 384, SMEM_K3>>>(grk, gbr, dv, W1, b1, W2, b2, out);
}

// round 8
// speedup vs baseline: 1.0261x; 1.0261x over previous
#include <cuda_runtime.h>
#include <cstdint>

// ------------------------- problem dims -------------------------
#define B_ 32
#define T_ 100
#define V_ 20000
#define E_ 128
#define H_ 128
#define M_ 64
#define ROWS_X (B_*T_)          // 3200
#define ROWS_TOT (ROWS_X + B_)  // 3232

// ------------------------- k1 config ----------------------------
#define CK 128                  // k per chunk (128 int8 = 128B rows, SW128)
#define NCH 157                 // ceil(20000/128)
#define NRT 26                  // row tiles of 128
#define NSPL 17                 // K splits
#define BASECH 9                // 157 = 4*10 + 13*9
#define EXTRA 4
#define GRID1 (NRT*NSPL)        // 442

// quantization scales: x: q=round(v*32512) (v in [0,1]); emb: q=round(v*325120)
#define SA_ 32512.0f
#define SB_ 325120.0f

// smem: AH[2][16K] AL[2][16K] BH[2][16K] BL[2][16K]
#define OFF_AH 0
#define OFF_AL 32768
#define OFF_BH 65536
#define OFF_BL 98304
#define SMEM_K1 131072

// k3 dynamic smem layout (floats)
#define K3_XP   0                    // [100*384]
#define K3_RP   (K3_XP + T_*384)     // [384]
#define K3_H    (K3_RP + 384)        // [128]
#define K3_MSK  (K3_H + 128)         // [100]
#define K3_CS   (K3_MSK + 100)       // [64]
#define SMEM_K3 ((K3_CS + 64 + 4) * 4)   // ~156.4 KB

// ------------------------- scratch globals ----------------------
__device__ float    g_parts[(size_t)NSPL * ROWS_TOT * 128];  // 28.1 MB
__device__ uint32_t g_ebh[(size_t)NCH * 4096];               // emb hi int8, tile-swizzled
__device__ uint32_t g_ebl[(size_t)NCH * 4096];               // emb lo int8
__device__ float    g_P[(size_t)ROWS_X * 384];
__device__ float    g_mask[ROWS_X];
__device__ float    g_ae[B_ * E_];

// ------------------------- helpers ------------------------------
__device__ __forceinline__ unsigned su32(const void* p) {
    return (unsigned)__cvta_generic_to_shared(p);
}
__device__ __forceinline__ void cpa16(unsigned dst, const void* src) {
    asm volatile("cp.async.ca.shared.global [%0], [%1], 16;\n"
                 :: "r"(dst), "l"(src));
}
__device__ __forceinline__ void ldsm4(uint32_t* r, uint32_t addr) {
    asm volatile("ldmatrix.sync.aligned.m8n8.x4.shared.b16 {%0,%1,%2,%3}, [%4];"
                 : "=r"(r[0]), "=r"(r[1]), "=r"(r[2]), "=r"(r[3]) : "r"(addr));
}
__device__ __forceinline__ void imma(int* c, const uint32_t* a, const uint32_t* b) {
    asm volatile("mma.sync.aligned.m16n8k32.row.col.s32.s8.s8.s32 "
                 "{%0,%1,%2,%3}, {%4,%5,%6,%7}, {%8,%9}, {%0,%1,%2,%3};"
                 : "+r"(c[0]), "+r"(c[1]), "+r"(c[2]), "+r"(c[3])
                 : "r"(a[0]), "r"(a[1]), "r"(a[2]), "r"(a[3]), "r"(b[0]), "r"(b[1]));
}
// quantize 4 floats -> hi/lo packed bytes (q = 256*hi + lo, hi,lo in s8)
__device__ __forceinline__ void quant4(float4 v, float scale, uint32_t& hw, uint32_t& lw) {
    int i0 = __float2int_rn(v.x * scale);
    int i1 = __float2int_rn(v.y * scale);
    int i2 = __float2int_rn(v.z * scale);
    int i3 = __float2int_rn(v.w * scale);
    int h0 = (i0 + 128) >> 8, h1 = (i1 + 128) >> 8;
    int h2 = (i2 + 128) >> 8, h3 = (i3 + 128) >> 8;
    int l0 = i0 - (h0 << 8), l1 = i1 - (h1 << 8);
    int l2 = i2 - (h2 << 8), l3 = i3 - (h3 << 8);
    hw = (h0 & 255) | ((h1 & 255) << 8) | ((h2 & 255) << 16) | ((h3 & 255) << 24);
    lw = (l0 & 255) | ((l1 & 255) << 8) | ((l2 & 255) << 16) | ((l3 & 255) << 24);
}

// fast transcendentals (MUFU-based, err ~2^-22)
#define LOG2E_ 1.4426950408889634f
__device__ __forceinline__ float ex2f(float x) {
    float r; asm("ex2.approx.f32 %0, %1;" : "=f"(r) : "f"(x)); return r;
}
__device__ __forceinline__ float rcpf(float x) {
    float r; asm("rcp.approx.f32 %0, %1;" : "=f"(r) : "f"(x)); return r;
}
__device__ __forceinline__ float sigmoid_f(float v) {
    return rcpf(1.f + ex2f(-v * LOG2E_));
}
__device__ __forceinline__ float tanh_f(float v) {
    return 1.f - 2.f * rcpf(ex2f(2.f * LOG2E_ * v) + 1.f);
}

// ---------------------------------------------------------------------------
// Kernel 0: emb -> transposed, int8 hi/lo split, SW128-swizzled 16KB tiles.
// ---------------------------------------------------------------------------
__global__ void __launch_bounds__(256) k0_prep(const float* __restrict__ emb)
{
    __shared__ float se[64][129];   // [kl][n]
    const int c = blockIdx.x, tid = threadIdx.x;
    uint32_t* oh = g_ebh + (size_t)c * 4096;
    uint32_t* ol = g_ebl + (size_t)c * 4096;

    for (int h = 0; h < 2; h++) {
        for (int i = tid; i < 64 * 128; i += 256) {
            int kl = i >> 7, r = i & 127;
            int k = c * CK + h * 64 + kl;
            se[kl][r] = (k < V_) ? emb[(size_t)k * E_ + r] : 0.f;
        }
        __syncthreads();

        for (int w = tid; w < 4096; w += 256) {
            uint32_t sw = 4u * w;
            int r = sw >> 7;
            int kb = (int)((sw & 127u) ^ ((uint32_t)(r & 7) << 4));
            if ((kb >> 6) == h) {
                int kl = kb & 63;
                float4 v = make_float4(se[kl][r], se[kl + 1][r],
                                       se[kl + 2][r], se[kl + 3][r]);
                uint32_t hw, lw;
                quant4(v, SB_, hw, lw);
                oh[w] = hw;
                ol[w] = lw;
            }
        }
        __syncthreads();
    }
}

// ---------------------------------------------------------------------------
// Kernel 1: 16-bit fixed-point GEMM via int8 IMMA (3 terms), split-K partials.
// 256 threads, 8 warps in 2(M)x4(N) grid, warp tile 64x32.
// sum = (65536*D + 256*E) / (SA*SB), D=ΣAhBh, E=Σ(AhBl+AlBh), ll dropped.
// ---------------------------------------------------------------------------
__global__ void __launch_bounds__(256, 1) k1_gemm(
    const float* __restrict__ x, const float* __restrict__ a_)
{
    extern __shared__ char smem[];
    const uint32_t sb = su32(smem);
    const int tid = threadIdx.x;
    const int lane = tid & 31;
    const int wid = tid >> 5;
    const int wm = wid >> 2;            // 0..1 (M halves of 64)
    const int wn = wid & 3;             // 0..3 (N quarters of 32)

    const int rt = blockIdx.x % NRT;
    const int sp = blockIdx.x / NRT;
    const int m0 = rt * 128;
    const int nch = BASECH + (sp < EXTRA ? 1 : 0);
    const int c0  = sp * BASECH + (sp < EXTRA ? sp : EXTRA);

    // ---- A loader mapping: 2 threads per row, 64 floats each ----
    const int arow = tid >> 1;          // 0..127
    const int aseg = tid & 1;           // k-half of 64 floats
    const uint32_t xs_a = (uint32_t)(arow & 7) << 4;

    const float* rowp;
    {
        int m = m0 + arow;
        if (m < ROWS_X)        rowp = x  + (size_t)m * V_;
        else if (m < ROWS_TOT) rowp = a_ + (size_t)(m - ROWS_X) * V_;
        else                   rowp = nullptr;
    }

    // ---- ldmatrix per-lane constants ----
    const int aq = lane >> 3;
    const int a_row_off = (aq & 1) * 8 + (lane & 7);
    const uint32_t a_kboff = (uint32_t)(aq >> 1) * 16;
    const int bjj = lane >> 4;
    const uint32_t b_kboff = (uint32_t)((lane >> 3) & 1) * 16;
    const uint32_t bbase0 = (uint32_t)(wn * 32 + 0 * 16 + bjj * 8 + (lane & 7)) * 128;
    const uint32_t bbase1 = (uint32_t)(wn * 32 + 1 * 16 + bjj * 8 + (lane & 7)) * 128;
    const uint32_t xorv = (uint32_t)(lane & 7) << 4;
    uint32_t abase[4];
    #pragma unroll
    for (int i = 0; i < 4; i++)
        abase[i] = (uint32_t)(wm * 64 + i * 16 + a_row_off) * 128;

    int accD[4][4][4], accE[4][4][4];   // [m-frag][n-frag][reg]
    #pragma unroll
    for (int i = 0; i < 4; i++)
        #pragma unroll
        for (int j = 0; j < 4; j++)
            #pragma unroll
            for (int q = 0; q < 4; q++) { accD[i][j][q] = 0; accE[i][j][q] = 0; }

    float4 av[8];   // one 32-float wave

    // wave w of chunk c: floats k = aseg*64 + w*32 + q*4
    auto loadA = [&](int c, int w) {
        #pragma unroll
        for (int q = 0; q < 8; q++) {
            int kb = c * CK + aseg * 64 + w * 32 + q * 4;
            av[q] = (rowp && kb < V_) ? *(const float4*)(rowp + kb)
                                      : make_float4(0.f, 0.f, 0.f, 0.f);
        }
    };
    auto stsA = [&](int s, int w) {
        const uint32_t ah = sb + OFF_AH + s * 16384 + arow * 128;
        const uint32_t al = sb + OFF_AL + s * 16384 + arow * 128;
        #pragma unroll
        for (int m = 0; m < 4; m++) {
            uint32_t H0, H1, L0, L1;
            quant4(av[2 * m],     SA_, H0, L0);
            quant4(av[2 * m + 1], SA_, H1, L1);
            uint32_t k = (uint32_t)(aseg * 64 + w * 32 + m * 8);
            uint32_t off = k ^ xs_a;
            asm volatile("st.shared.v2.b32 [%0], {%1,%2};" :: "r"(ah + off), "r"(H0), "r"(H1));
            asm volatile("st.shared.v2.b32 [%0], {%1,%2};" :: "r"(al + off), "r"(L0), "r"(L1));
        }
    };
    auto cpB = [&](int c, int s) {
        const char* srcH = (const char*)g_ebh + (size_t)c * 16384;
        const char* srcL = (const char*)g_ebl + (size_t)c * 16384;
        const uint32_t bh = sb + OFF_BH + s * 16384;
        const uint32_t bl = sb + OFF_BL + s * 16384;
        #pragma unroll
        for (int j = 0; j < 4; j++) {
            int off = (j * 256 + tid) * 16;
            cpa16(bh + off, srcH + off);
            cpa16(bl + off, srcL + off);
        }
        asm volatile("cp.async.commit_group;");
    };

    // one ks-step of MMAs on buffer s
    auto mmaStep = [&](int s, int ks) {
        const uint32_t ahs = sb + OFF_AH + s * 16384;
        const uint32_t als = sb + OFF_AL + s * 16384;
        const uint32_t bhs = sb + OFF_BH + s * 16384;
        const uint32_t bls = sb + OFF_BL + s * 16384;
        const uint32_t kta = ((uint32_t)(ks * 32) + a_kboff) ^ xorv;
        const uint32_t ktb = ((uint32_t)(ks * 32) + b_kboff) ^ xorv;
        uint32_t ah[4][4], al[4][4], bh[2][4], bl[2][4];
        #pragma unroll
        for (int i = 0; i < 4; i++) {
            ldsm4(ah[i], ahs + abase[i] + kta);
            ldsm4(al[i], als + abase[i] + kta);
        }
        ldsm4(bh[0], bhs + bbase0 + ktb);
        ldsm4(bh[1], bhs + bbase1 + ktb);
        ldsm4(bl[0], bls + bbase0 + ktb);
        ldsm4(bl[1], bls + bbase1 + ktb);
        #pragma unroll
        for (int i = 0; i < 4; i++) {
            #pragma unroll
            for (int j = 0; j < 4; j++) {
                const uint32_t* bhp = &bh[j >> 1][(j & 1) * 2];
                const uint32_t* blp = &bl[j >> 1][(j & 1) * 2];
                imma(accD[i][j], ah[i], bhp);
                imma(accE[i][j], ah[i], blp);
                imma(accE[i][j], al[i], bhp);
            }
        }
    };

    // ---- prologue: fill buffer 0, prefetch wave0 of chunk 1 ----
    loadA(c0, 0); stsA(0, 0);
    loadA(c0, 1); stsA(0, 1);
    cpB(c0, 0);
    if (nch > 1) loadA(c0 + 1, 0);

    for (int t = 0; t < nch; t++) {
        const int s = t & 1;
        asm volatile("cp.async.wait_group 0;" ::: "memory");
        __syncthreads();   // buf s ready (B cp.async + A STS), buf s^1 free

        if (t + 1 < nch) { cpB(c0 + t + 1, s ^ 1); stsA(s ^ 1, 0); }
        mmaStep(s, 0);
        mmaStep(s, 1);
        if (t + 1 < nch) loadA(c0 + t + 1, 1);
        mmaStep(s, 2);
        mmaStep(s, 3);
        if (t + 1 < nch) stsA(s ^ 1, 1);
        if (t + 2 < nch) loadA(c0 + t + 2, 0);
    }

    // ---- epilogue: dequantize + write this split's partial tile ----
    const float INVQ = 1.0f / (SA_ * SB_);
    const int gid = lane >> 2, tig = lane & 3;
    #pragma unroll
    for (int i = 0; i < 4; i++) {
        int mrow = m0 + wm * 64 + i * 16 + gid;
        #pragma unroll
        for (int j = 0; j < 4; j++) {
            int n = wn * 32 + j * 8 + tig * 2;
            float v0 = fmaf((float)accD[i][j][0], 65536.f, (float)accE[i][j][0] * 256.f) * INVQ;
            float v1 = fmaf((float)accD[i][j][1], 65536.f, (float)accE[i][j][1] * 256.f) * INVQ;
            float v2 = fmaf((float)accD[i][j][2], 65536.f, (float)accE[i][j][2] * 256.f) * INVQ;
            float v3 = fmaf((float)accD[i][j][3], 65536.f, (float)accE[i][j][3] * 256.f) * INVQ;
            if (mrow < ROWS_TOT) {
                float* d0 = g_parts + ((size_t)sp * ROWS_TOT + mrow) * 128 + n;
                *(float2*)d0 = make_float2(v0, v1);
            }
            if (mrow + 8 < ROWS_TOT) {
                float* d1 = g_parts + ((size_t)sp * ROWS_TOT + mrow + 8) * 128 + n;
                *(float2*)d1 = make_float2(v2, v3);
            }
        }
    }
}

// ---------------------------------------------------------------------------
// Kernel 2: reduce partials + tanh -> xe; mask; x_proj = xe@gru_k + b_i.
// ---------------------------------------------------------------------------
__global__ void __launch_bounds__(128) k2_reduce_proj(
    const float* __restrict__ gk, const float* __restrict__ gbi)
{
    __shared__ float xs[16][128];
    __shared__ int nz[16];
    const int tid = threadIdx.x;
    const int r0 = blockIdx.x * 16;

    if (tid < 16) nz[tid] = 0;
    __syncthreads();

    for (int i = tid; i < 16 * 128; i += 128) {
        int r = i >> 7, n = i & 127;
        int m = r0 + r;
        float s = 0.f;
        const float* pp = g_parts + (size_t)m * 128 + n;
        #pragma unroll
        for (int sp = 0; sp < NSPL; sp++) s += pp[(size_t)sp * ROWS_TOT * 128];
        float v = tanh_f(s);
        xs[r][n] = v;
        if (v != 0.f) nz[r] = 1;
    }
    __syncthreads();

    if (r0 < ROWS_X) {
        float acc[16][3];
        #pragma unroll
        for (int r = 0; r < 16; r++) { acc[r][0] = 0.f; acc[r][1] = 0.f; acc[r][2] = 0.f; }
        for (int k = 0; k < 128; k++) {
            float w0 = gk[k * 384 + tid];
            float w1 = gk[k * 384 + 128 + tid];
            float w2 = gk[k * 384 + 256 + tid];
            #pragma unroll
            for (int r = 0; r < 16; r++) {
                float xv = xs[r][k];
                acc[r][0] = fmaf(xv, w0, acc[r][0]);
                acc[r][1] = fmaf(xv, w1, acc[r][1]);
                acc[r][2] = fmaf(xv, w2, acc[r][2]);
            }
        }
        float bb0 = gbi[tid], bb1 = gbi[128 + tid], bb2 = gbi[256 + tid];
        #pragma unroll
        for (int r = 0; r < 16; r++) {
            size_t m = (size_t)(r0 + r);
            g_P[m * 384 + tid]       = acc[r][0] + bb0;
            g_P[m * 384 + 128 + tid] = acc[r][1] + bb1;
            g_P[m * 384 + 256 + tid] = acc[r][2] + bb2;
        }
        if (tid < 16) g_mask[r0 + tid] = nz[tid] ? 1.f : 0.f;
    } else {
        for (int i = tid; i < 16 * 128; i += 128) {
            int r = i >> 7, n = i & 127;
            g_ae[(r0 - ROWS_X + r) * 128 + n] = xs[r][n];
        }
    }
}

// ---------------------------------------------------------------------------
// Kernel 3: per-batch GRU + head. 32 CTAs x 384 threads. x_proj + masks fully
// resident in dynamic smem; zero global traffic inside the recurrence loop.
// ---------------------------------------------------------------------------
__global__ void __launch_bounds__(384, 1) k3_gru(
    const float* __restrict__ grk, const float* __restrict__ gbr,
    const float* __restrict__ dvec, const float* __restrict__ W1,
    const float* __restrict__ b1, const float* __restrict__ W2,
    const float* __restrict__ b2, float* __restrict__ out)
{
    extern __shared__ float sm3[];
    float* xp  = sm3 + K3_XP;
    float* rp  = sm3 + K3_RP;
    float* h_s = sm3 + K3_H;
    float* msk = sm3 + K3_MSK;
    float* cs  = sm3 + K3_CS;

    const int tid = threadIdx.x;
    const int b = blockIdx.x;

    {
        const float* src = g_P + (size_t)b * T_ * 384;
        #pragma unroll
        for (int it = 0; it < 25; it++) {
            int i = it * 1536 + tid * 4;
            cpa16(su32(xp + i), src + i);
        }
        if (tid < 25) cpa16(su32(msk + tid * 4), g_mask + b * T_ + tid * 4);
        asm volatile("cp.async.commit_group;");
    }

    unsigned long long w2[64];
    #pragma unroll
    for (int q = 0; q < 64; q++) {
        float w0 = grk[(2 * q)     * 384 + tid];
        float w1 = grk[(2 * q + 1) * 384 + tid];
        asm("mov.b64 %0, {%1, %2};" : "=l"(w2[q]) : "f"(w0), "f"(w1));
    }
    const float bias = gbr[tid];

    if (tid < 128) h_s[tid] = 0.f;
    asm volatile("cp.async.wait_group 0;" ::: "memory");
    __syncthreads();

    for (int t = 0; t < T_; t++) {
        unsigned long long a0 = 0ULL, a1 = 0ULL, a2 = 0ULL, a3 = 0ULL;
        #pragma unroll
        for (int q = 0; q < 8; q++) {
            ulonglong2 u0 = *(const ulonglong2*)&h_s[q * 4];
            ulonglong2 u1 = *(const ulonglong2*)&h_s[32 + q * 4];
            ulonglong2 u2 = *(const ulonglong2*)&h_s[64 + q * 4];
            ulonglong2 u3 = *(const ulonglong2*)&h_s[96 + q * 4];
            asm("fma.rn.f32x2 %0, %1, %2, %0;" : "+l"(a0) : "l"(u0.x), "l"(w2[2 * q]));
            asm("fma.rn.f32x2 %0, %1, %2, %0;" : "+l"(a1) : "l"(u1.x), "l"(w2[16 + 2 * q]));
            asm("fma.rn.f32x2 %0, %1, %2, %0;" : "+l"(a2) : "l"(u2.x), "l"(w2[32 + 2 * q]));
            asm("fma.rn.f32x2 %0, %1, %2, %0;" : "+l"(a3) : "l"(u3.x), "l"(w2[48 + 2 * q]));
            asm("fma.rn.f32x2 %0, %1, %2, %0;" : "+l"(a0) : "l"(u0.y), "l"(w2[2 * q + 1]));
            asm("fma.rn.f32x2 %0, %1, %2, %0;" : "+l"(a1) : "l"(u1.y), "l"(w2[16 + 2 * q + 1]));
            asm("fma.rn.f32x2 %0, %1, %2, %0;" : "+l"(a2) : "l"(u2.y), "l"(w2[32 + 2 * q + 1]));
            asm("fma.rn.f32x2 %0, %1, %2, %0;" : "+l"(a3) : "l"(u3.y), "l"(w2[48 + 2 * q + 1]));
        }
        float s0, s1, s2, s3, s4, s5, s6, s7;
        asm("mov.b64 {%0, %1}, %2;" : "=f"(s0), "=f"(s1) : "l"(a0));
        asm("mov.b64 {%0, %1}, %2;" : "=f"(s2), "=f"(s3) : "l"(a1));
        asm("mov.b64 {%0, %1}, %2;" : "=f"(s4), "=f"(s5) : "l"(a2));
        asm("mov.b64 {%0, %1}, %2;" : "=f"(s6), "=f"(s7) : "l"(a3));
        rp[tid] = ((s0 + s1) + (s2 + s3)) + ((s4 + s5) + (s6 + s7)) + bias;
        __syncthreads();

        if (tid < 128) {
            const float* xpc = xp + t * 384;
            float z  = sigmoid_f(xpc[tid] + rp[tid]);
            float r  = sigmoid_f(xpc[tid + 128] + rp[tid + 128]);
            float hh = tanh_f(xpc[tid + 256] + r * rp[tid + 256]);
            float hprev = h_s[tid];
            float hn = z * hprev + (1.f - z) * hh;
            h_s[tid] = (msk[t] != 0.f) ? hn : hprev;
        }
        __syncthreads();
    }

    if (tid < 64) {
        float acc = b1[tid];
        const float* ae = g_ae + b * 128;
        #pragma unroll 4
        for (int k = 0; k < 128; k++) acc = fmaf(h_s[k], W1[k * 64 + tid], acc);
        #pragma unroll 4
        for (int k = 0; k < 128; k++) acc = fmaf(ae[k], W1[(128 + k) * 64 + tid], acc);
        cs[tid] = tanh_f(acc) * W2[tid];
    }
    __syncthreads();
    if (tid == 0) {
        float s = 0.f;
        #pragma unroll 8
        for (int i = 0; i < 64; i++) s += cs[i];
        s += dvec[b * 2] * W2[64] + dvec[b * 2 + 1] * W2[65] + b2[0];
        out[b] = sigmoid_f(s);
    }
}

// ---------------------------------------------------------------------------
extern "C" void kernel_launch(void* const* d_in, const int* in_sizes, int n_in,
                              void* d_out, int out_size)
{
    const float* x   = (const float*)d_in[0];
    const float* a   = (const float*)d_in[1];
    const float* dv  = (const float*)d_in[2];
    const float* emb = (const float*)d_in[3];
    const float* gk  = (const float*)d_in[4];
    const float* grk = (const float*)d_in[5];
    const float* gbi = (const float*)d_in[6];
    const float* gbr = (const float*)d_in[7];
    const float* W1  = (const float*)d_in[8];
    const float* b1  = (const float*)d_in[9];
    const float* W2  = (const float*)d_in[10];
    const float* b2  = (const float*)d_in[11];
    float* out = (float*)d_out;

    cudaFuncSetAttribute(k1_gemm, cudaFuncAttributeMaxDynamicSharedMemorySize, SMEM_K1);
    cudaFuncSetAttribute(k3_gru,  cudaFuncAttributeMaxDynamicSharedMemorySize, SMEM_K3);

    k0_prep<<<NCH, 256>>>(emb);
    k1_gemm<<<GRID1, 256, SMEM_K1>>>(x, a);
    k2_reduce_proj<<<ROWS_TOT / 16, 128>>>(gk, gbi);
    k3_gru<<<B_, 384, SMEM_K3>>>(grk, gbr, dv, W1, b1, W2, b2, out);
}

// round 9
// speedup vs baseline: 1.9550x; 1.9053x over previous
#include <cuda_runtime.h>
#include <cstdint>

// ------------------------- problem dims -------------------------
#define B_ 32
#define T_ 100
#define V_ 20000
#define E_ 128
#define H_ 128
#define M_ 64
#define ROWS_X (B_*T_)          // 3200
#define ROWS_TOT (ROWS_X + B_)  // 3232

// ------------------------- k1 config ----------------------------
#define CK 64                   // k per chunk (64 bf16 = 128B rows, SW128)
#define NCH 313                 // ceil(20000/64)
#define NRT 51                  // row tiles of 64 (3264 rows padded)
#define NSPL 17                 // K splits
#define BASECH 18               // 313 = 7*19 + 10*18
#define EXTRA 7
#define GRID1 (NRT*NSPL)        // 867  (~2.93 waves at 2 CTAs/SM)

// per-stage smem block: AH 8K | AL 8K | BH 16K | BL 16K  = 48KB
#define STG_BYTES 49152
#define OFF_AH 0
#define OFF_AL 8192
#define OFF_BH 16384
#define OFF_BL 32768
#define SMEM_K1 (2*STG_BYTES)   // 96KB -> 2 CTAs/SM

// k3 dynamic smem layout (floats)
#define K3_XP   0                    // [100*384]
#define K3_RP   (K3_XP + T_*384)     // [384]
#define K3_H    (K3_RP + 384)        // [128]
#define K3_MSK  (K3_H + 128)         // [100]
#define K3_CS   (K3_MSK + 100)       // [64]
#define SMEM_K3 ((K3_CS + 64 + 4) * 4)   // ~156.4 KB

// ------------------------- scratch globals ----------------------
__device__ float    g_parts[(size_t)NSPL * ROWS_TOT * 128];  // 28.1 MB
__device__ uint32_t g_ebh[(size_t)NCH * 4096];               // emb hi bf16, tile-swizzled
__device__ uint32_t g_ebl[(size_t)NCH * 4096];               // emb lo bf16
__device__ float    g_P[(size_t)ROWS_X * 384];
__device__ float    g_mask[ROWS_X];
__device__ float    g_ae[B_ * E_];

// ------------------------- helpers ------------------------------
__device__ __forceinline__ unsigned su32(const void* p) {
    return (unsigned)__cvta_generic_to_shared(p);
}
__device__ __forceinline__ void cpa16(unsigned dst, const void* src) {
    asm volatile("cp.async.ca.shared.global [%0], [%1], 16;\n"
                 :: "r"(dst), "l"(src));
}
__device__ __forceinline__ void ldsm4(uint32_t* r, uint32_t addr) {
    asm volatile("ldmatrix.sync.aligned.m8n8.x4.shared.b16 {%0,%1,%2,%3}, [%4];"
                 : "=r"(r[0]), "=r"(r[1]), "=r"(r[2]), "=r"(r[3]) : "r"(addr));
}
__device__ __forceinline__ void mma16816(float* c, const uint32_t* a, const uint32_t* b) {
    asm volatile("mma.sync.aligned.m16n8k16.row.col.f32.bf16.bf16.f32 "
                 "{%0,%1,%2,%3}, {%4,%5,%6,%7}, {%8,%9}, {%0,%1,%2,%3};"
                 : "+f"(c[0]), "+f"(c[1]), "+f"(c[2]), "+f"(c[3])
                 : "r"(a[0]), "r"(a[1]), "r"(a[2]), "r"(a[3]), "r"(b[0]), "r"(b[1]));
}

// fast transcendentals (MUFU-based, err ~2^-22)
#define LOG2E_ 1.4426950408889634f
__device__ __forceinline__ float ex2f(float x) {
    float r; asm("ex2.approx.f32 %0, %1;" : "=f"(r) : "f"(x)); return r;
}
__device__ __forceinline__ float rcpf(float x) {
    float r; asm("rcp.approx.f32 %0, %1;" : "=f"(r) : "f"(x)); return r;
}
__device__ __forceinline__ float sigmoid_f(float v) {
    return rcpf(1.f + ex2f(-v * LOG2E_));
}
__device__ __forceinline__ float tanh_f(float v) {
    return 1.f - 2.f * rcpf(ex2f(2.f * LOG2E_ * v) + 1.f);
}

// ---------------------------------------------------------------------------
// Kernel 0: emb -> transposed, bf16 hi/lo split, SW128-swizzled 16KB tiles.
// Tile c: [n=0..127 rows][k=0..63 bf16], 128B rows. One CTA per chunk.
// ---------------------------------------------------------------------------
__global__ void __launch_bounds__(256) k0_prep(const float* __restrict__ emb)
{
    __shared__ float se[64][129];   // [kl][n]
    const int c = blockIdx.x, tid = threadIdx.x;

    for (int i = tid; i < 64 * 128; i += 256) {
        int kl = i >> 7, r = i & 127;
        int k = c * CK + kl;
        se[kl][r] = (k < V_) ? emb[(size_t)k * E_ + r] : 0.f;
    }
    __syncthreads();

    uint32_t* oh = g_ebh + (size_t)c * 4096;
    uint32_t* ol = g_ebl + (size_t)c * 4096;
    for (int p = tid; p < 4096; p += 256) {
        uint32_t bo = p * 4;
        uint32_t lg = bo ^ ((bo >> 3) & 0x70);   // swizzle is an involution
        int r = lg >> 7, kl0 = (lg & 127) >> 1;
        float v0 = se[kl0][r], v1 = se[kl0 + 1][r];
        uint32_t hw, lw;
        asm("cvt.rn.bf16x2.f32 %0, %1, %2;" : "=r"(hw) : "f"(v1), "f"(v0));
        float h0 = __uint_as_float(hw << 16);
        float h1 = __uint_as_float(hw & 0xFFFF0000u);
        asm("cvt.rn.bf16x2.f32 %0, %1, %2;" : "=r"(lw) : "f"(v1 - h1), "f"(v0 - h0));
        oh[p] = hw;
        ol[p] = lw;
    }
}

// ---------------------------------------------------------------------------
// Kernel 1: split-bf16 GEMM via ldmatrix + mma.sync (HMMA), split-K partials.
// 256 threads, 8 warps in 2(M)x4(N) grid of 32x32 warp tiles; CTA tile 64x128.
// 2-stage pipeline, 96KB smem -> 2 CTAs/SM for cross-CTA latency hiding.
// ---------------------------------------------------------------------------
__global__ void __launch_bounds__(256, 2) k1_gemm(
    const float* __restrict__ x, const float* __restrict__ a_)
{
    extern __shared__ char smem[];
    const uint32_t sb = su32(smem);
    const int tid = threadIdx.x;
    const int lane = tid & 31;
    const int wid = tid >> 5;
    const int wm = wid >> 2;            // 0..1 (M halves of 32)
    const int wn = wid & 3;             // 0..3 (N quarters of 32)

    const int rt = blockIdx.x % NRT;
    const int sp = blockIdx.x / NRT;
    const int m0 = rt * 64;
    const int nch = BASECH + (sp < EXTRA ? 1 : 0);
    const int c0  = sp * BASECH + (sp < EXTRA ? sp : EXTRA);

    // ---- A loader mapping: 4 threads per row, 16 floats each ----
    const int arow = tid >> 2;          // 0..63
    const int acol4 = tid & 3;
    const uint32_t xs_a = (uint32_t)(arow & 7) << 4;

    const float* rowp;
    {
        int m = m0 + arow;
        if (m < ROWS_X)        rowp = x  + (size_t)m * V_;
        else if (m < ROWS_TOT) rowp = a_ + (size_t)(m - ROWS_X) * V_;
        else                   rowp = nullptr;
    }

    // ---- ldmatrix per-lane constants (identical to proven R4 mapping) ----
    const int aq = lane >> 3;
    const int a_row_off = (aq & 1) * 8 + (lane & 7);
    const uint32_t a_kboff = (uint32_t)(aq >> 1) * 16;
    const uint32_t abase0 = (uint32_t)(wm * 32 + 0 * 16 + a_row_off) * 128;
    const uint32_t abase1 = (uint32_t)(wm * 32 + 1 * 16 + a_row_off) * 128;
    const int bjj = lane >> 4;
    const uint32_t b_kboff = (uint32_t)((lane >> 3) & 1) * 16;
    const uint32_t bbase0 = (uint32_t)(wn * 32 + 0 * 16 + bjj * 8 + (lane & 7)) * 128;
    const uint32_t bbase1 = (uint32_t)(wn * 32 + 1 * 16 + bjj * 8 + (lane & 7)) * 128;
    const uint32_t xorv = (uint32_t)(lane & 7) << 4;

    float acc[2][4][4];
    #pragma unroll
    for (int i = 0; i < 2; i++)
        #pragma unroll
        for (int j = 0; j < 4; j++)
            #pragma unroll
            for (int q = 0; q < 4; q++) acc[i][j][q] = 0.f;

    float4 av[4];

    auto loadA = [&](int c) {
        #pragma unroll
        for (int q = 0; q < 4; q++) {
            int kb = c * CK + q * 16 + acol4 * 4;
            av[q] = (rowp && kb < V_) ? *(const float4*)(rowp + kb)
                                      : make_float4(0.f, 0.f, 0.f, 0.f);
        }
    };
    auto stsA = [&](int s) {
        const uint32_t ah = sb + s * STG_BYTES + OFF_AH + arow * 128;
        const uint32_t al = sb + s * STG_BYTES + OFF_AL + arow * 128;
        #pragma unroll
        for (int q = 0; q < 4; q++) {
            uint32_t ina = ((uint32_t)(q * 32 + acol4 * 8)) ^ xs_a;
            float4 v = av[q];
            uint32_t h0, h1, l0, l1;
            asm("cvt.rn.bf16x2.f32 %0, %1, %2;" : "=r"(h0) : "f"(v.y), "f"(v.x));
            asm("cvt.rn.bf16x2.f32 %0, %1, %2;" : "=r"(h1) : "f"(v.w), "f"(v.z));
            float hx = __uint_as_float(h0 << 16), hy = __uint_as_float(h0 & 0xFFFF0000u);
            float hz = __uint_as_float(h1 << 16), hw_ = __uint_as_float(h1 & 0xFFFF0000u);
            asm("cvt.rn.bf16x2.f32 %0, %1, %2;" : "=r"(l0) : "f"(v.y - hy), "f"(v.x - hx));
            asm("cvt.rn.bf16x2.f32 %0, %1, %2;" : "=r"(l1) : "f"(v.w - hw_), "f"(v.z - hz));
            asm volatile("st.shared.v2.b32 [%0], {%1,%2};" :: "r"(ah + ina), "r"(h0), "r"(h1));
            asm volatile("st.shared.v2.b32 [%0], {%1,%2};" :: "r"(al + ina), "r"(l0), "r"(l1));
        }
    };
    auto cpB = [&](int c, int s) {
        const char* srcH = (const char*)g_ebh + (size_t)c * 16384;
        const char* srcL = (const char*)g_ebl + (size_t)c * 16384;
        const uint32_t bh = sb + s * STG_BYTES + OFF_BH;
        const uint32_t bl = sb + s * STG_BYTES + OFF_BL;
        #pragma unroll
        for (int j = 0; j < 4; j++) {
            int off = (j * 256 + tid) * 16;
            cpa16(bh + off, srcH + off);
            cpa16(bl + off, srcL + off);
        }
        asm volatile("cp.async.commit_group;");
    };

    auto mmaStep = [&](int s, int ks) {
        const uint32_t ahs = sb + s * STG_BYTES + OFF_AH;
        const uint32_t als = sb + s * STG_BYTES + OFF_AL;
        const uint32_t bhs = sb + s * STG_BYTES + OFF_BH;
        const uint32_t bls = sb + s * STG_BYTES + OFF_BL;
        const uint32_t kta = ((uint32_t)(ks * 32) + a_kboff) ^ xorv;
        const uint32_t ktb = ((uint32_t)(ks * 32) + b_kboff) ^ xorv;
        uint32_t ah0[4], ah1[4], al0[4], al1[4], bh[2][4], bl[2][4];
        ldsm4(ah0, ahs + abase0 + kta);
        ldsm4(ah1, ahs + abase1 + kta);
        ldsm4(al0, als + abase0 + kta);
        ldsm4(al1, als + abase1 + kta);
        ldsm4(bh[0], bhs + bbase0 + ktb);
        ldsm4(bh[1], bhs + bbase1 + ktb);
        ldsm4(bl[0], bls + bbase0 + ktb);
        ldsm4(bl[1], bls + bbase1 + ktb);
        #pragma unroll
        for (int j = 0; j < 4; j++) {
            const uint32_t* bhp = &bh[j >> 1][(j & 1) * 2];
            const uint32_t* blp = &bl[j >> 1][(j & 1) * 2];
            mma16816(acc[0][j], ah0, bhp);
            mma16816(acc[0][j], ah0, blp);
            mma16816(acc[0][j], al0, bhp);
            mma16816(acc[1][j], ah1, bhp);
            mma16816(acc[1][j], ah1, blp);
            mma16816(acc[1][j], al1, bhp);
        }
    };

    // ---- prologue ----
    loadA(c0);
    stsA(0);
    cpB(c0, 0);
    if (nch > 1) loadA(c0 + 1);

    for (int t = 0; t < nch; t++) {
        const int s = t & 1;
        asm volatile("cp.async.wait_group 0;" ::: "memory");
        __syncthreads();   // buf s ready; all warps done reading buf s^1

        if (t + 1 < nch) {
            cpB(c0 + t + 1, s ^ 1);
            stsA(s ^ 1);
        }
        mmaStep(s, 0);
        mmaStep(s, 1);
        if (t + 2 < nch) loadA(c0 + t + 2);
        mmaStep(s, 2);
        mmaStep(s, 3);
    }

    // ---- epilogue: write this split's partial tile ----
    const int gid = lane >> 2, tig = lane & 3;
    #pragma unroll
    for (int i = 0; i < 2; i++) {
        int mrow = m0 + wm * 32 + i * 16 + gid;
        #pragma unroll
        for (int j = 0; j < 4; j++) {
            int n = wn * 32 + j * 8 + tig * 2;
            if (mrow < ROWS_TOT) {
                float* d0 = g_parts + ((size_t)sp * ROWS_TOT + mrow) * 128 + n;
                *(float2*)d0 = make_float2(acc[i][j][0], acc[i][j][1]);
            }
            if (mrow + 8 < ROWS_TOT) {
                float* d1 = g_parts + ((size_t)sp * ROWS_TOT + mrow + 8) * 128 + n;
                *(float2*)d1 = make_float2(acc[i][j][2], acc[i][j][3]);
            }
        }
    }
}

// ---------------------------------------------------------------------------
// Kernel 2: reduce partials + tanh -> xe; mask; x_proj = xe@gru_k + b_i.
// ---------------------------------------------------------------------------
__global__ void __launch_bounds__(128) k2_reduce_proj(
    const float* __restrict__ gk, const float* __restrict__ gbi)
{
    __shared__ float xs[16][128];
    __shared__ int nz[16];
    const int tid = threadIdx.x;
    const int r0 = blockIdx.x * 16;

    if (tid < 16) nz[tid] = 0;
    __syncthreads();

    for (int i = tid; i < 16 * 128; i += 128) {
        int r = i >> 7, n = i & 127;
        int m = r0 + r;
        float s = 0.f;
        const float* pp = g_parts + (size_t)m * 128 + n;
        #pragma unroll
        for (int sp = 0; sp < NSPL; sp++) s += pp[(size_t)sp * ROWS_TOT * 128];
        float v = tanh_f(s);
        xs[r][n] = v;
        if (v != 0.f) nz[r] = 1;
    }
    __syncthreads();

    if (r0 < ROWS_X) {
        float acc[16][3];
        #pragma unroll
        for (int r = 0; r < 16; r++) { acc[r][0] = 0.f; acc[r][1] = 0.f; acc[r][2] = 0.f; }
        for (int k = 0; k < 128; k++) {
            float w0 = gk[k * 384 + tid];
            float w1 = gk[k * 384 + 128 + tid];
            float w2 = gk[k * 384 + 256 + tid];
            #pragma unroll
            for (int r = 0; r < 16; r++) {
                float xv = xs[r][k];
                acc[r][0] = fmaf(xv, w0, acc[r][0]);
                acc[r][1] = fmaf(xv, w1, acc[r][1]);
                acc[r][2] = fmaf(xv, w2, acc[r][2]);
            }
        }
        float bb0 = gbi[tid], bb1 = gbi[128 + tid], bb2 = gbi[256 + tid];
        #pragma unroll
        for (int r = 0; r < 16; r++) {
            size_t m = (size_t)(r0 + r);
            g_P[m * 384 + tid]       = acc[r][0] + bb0;
            g_P[m * 384 + 128 + tid] = acc[r][1] + bb1;
            g_P[m * 384 + 256 + tid] = acc[r][2] + bb2;
        }
        if (tid < 16) g_mask[r0 + tid] = nz[tid] ? 1.f : 0.f;
    } else {
        for (int i = tid; i < 16 * 128; i += 128) {
            int r = i >> 7, n = i & 127;
            g_ae[(r0 - ROWS_X + r) * 128 + n] = xs[r][n];
        }
    }
}

// ---------------------------------------------------------------------------
// Kernel 3: per-batch GRU + head. 32 CTAs x 384 threads. x_proj + masks fully
// resident in dynamic smem; zero global traffic inside the recurrence loop.
// ---------------------------------------------------------------------------
__global__ void __launch_bounds__(384, 1) k3_gru(
    const float* __restrict__ grk, const float* __restrict__ gbr,
    const float* __restrict__ dvec, const float* __restrict__ W1,
    const float* __restrict__ b1, const float* __restrict__ W2,
    const float* __restrict__ b2, float* __restrict__ out)
{
    extern __shared__ float sm3[];
    float* xp  = sm3 + K3_XP;
    float* rp  = sm3 + K3_RP;
    float* h_s = sm3 + K3_H;
    float* msk = sm3 + K3_MSK;
    float* cs  = sm3 + K3_CS;

    const int tid = threadIdx.x;
    const int b = blockIdx.x;

    {
        const float* src = g_P + (size_t)b * T_ * 384;
        #pragma unroll
        for (int it = 0; it < 25; it++) {
            int i = it * 1536 + tid * 4;
            cpa16(su32(xp + i), src + i);
        }
        if (tid < 25) cpa16(su32(msk + tid * 4), g_mask + b * T_ + tid * 4);
        asm volatile("cp.async.commit_group;");
    }

    unsigned long long w2[64];
    #pragma unroll
    for (int q = 0; q < 64; q++) {
        float w0 = grk[(2 * q)     * 384 + tid];
        float w1 = grk[(2 * q + 1) * 384 + tid];
        asm("mov.b64 %0, {%1, %2};" : "=l"(w2[q]) : "f"(w0), "f"(w1));
    }
    const float bias = gbr[tid];

    if (tid < 128) h_s[tid] = 0.f;
    asm volatile("cp.async.wait_group 0;" ::: "memory");
    __syncthreads();

    for (int t = 0; t < T_; t++) {
        unsigned long long a0 = 0ULL, a1 = 0ULL, a2 = 0ULL, a3 = 0ULL;
        #pragma unroll
        for (int q = 0; q < 8; q++) {
            ulonglong2 u0 = *(const ulonglong2*)&h_s[q * 4];
            ulonglong2 u1 = *(const ulonglong2*)&h_s[32 + q * 4];
            ulonglong2 u2 = *(const ulonglong2*)&h_s[64 + q * 4];
            ulonglong2 u3 = *(const ulonglong2*)&h_s[96 + q * 4];
            asm("fma.rn.f32x2 %0, %1, %2, %0;" : "+l"(a0) : "l"(u0.x), "l"(w2[2 * q]));
            asm("fma.rn.f32x2 %0, %1, %2, %0;" : "+l"(a1) : "l"(u1.x), "l"(w2[16 + 2 * q]));
            asm("fma.rn.f32x2 %0, %1, %2, %0;" : "+l"(a2) : "l"(u2.x), "l"(w2[32 + 2 * q]));
            asm("fma.rn.f32x2 %0, %1, %2, %0;" : "+l"(a3) : "l"(u3.x), "l"(w2[48 + 2 * q]));
            asm("fma.rn.f32x2 %0, %1, %2, %0;" : "+l"(a0) : "l"(u0.y), "l"(w2[2 * q + 1]));
            asm("fma.rn.f32x2 %0, %1, %2, %0;" : "+l"(a1) : "l"(u1.y), "l"(w2[16 + 2 * q + 1]));
            asm("fma.rn.f32x2 %0, %1, %2, %0;" : "+l"(a2) : "l"(u2.y), "l"(w2[32 + 2 * q + 1]));
            asm("fma.rn.f32x2 %0, %1, %2, %0;" : "+l"(a3) : "l"(u3.y), "l"(w2[48 + 2 * q + 1]));
        }
        float s0, s1, s2, s3, s4, s5, s6, s7;
        asm("mov.b64 {%0, %1}, %2;" : "=f"(s0), "=f"(s1) : "l"(a0));
        asm("mov.b64 {%0, %1}, %2;" : "=f"(s2), "=f"(s3) : "l"(a1));
        asm("mov.b64 {%0, %1}, %2;" : "=f"(s4), "=f"(s5) : "l"(a2));
        asm("mov.b64 {%0, %1}, %2;" : "=f"(s6), "=f"(s7) : "l"(a3));
        rp[tid] = ((s0 + s1) + (s2 + s3)) + ((s4 + s5) + (s6 + s7)) + bias;
        __syncthreads();

        if (tid < 128) {
            const float* xpc = xp + t * 384;
            float z  = sigmoid_f(xpc[tid] + rp[tid]);
            float r  = sigmoid_f(xpc[tid + 128] + rp[tid + 128]);
            float hh = tanh_f(xpc[tid + 256] + r * rp[tid + 256]);
            float hprev = h_s[tid];
            float hn = z * hprev + (1.f - z) * hh;
            h_s[tid] = (msk[t] != 0.f) ? hn : hprev;
        }
        __syncthreads();
    }

    if (tid < 64) {
        float acc = b1[tid];
        const float* ae = g_ae + b * 128;
        #pragma unroll 4
        for (int k = 0; k < 128; k++) acc = fmaf(h_s[k], W1[k * 64 + tid], acc);
        #pragma unroll 4
        for (int k = 0; k < 128; k++) acc = fmaf(ae[k], W1[(128 + k) * 64 + tid], acc);
        cs[tid] = tanh_f(acc) * W2[tid];
    }
    __syncthreads();
    if (tid == 0) {
        float s = 0.f;
        #pragma unroll 8
        for (int i = 0; i < 64; i++) s += cs[i];
        s += dvec[b * 2] * W2[64] + dvec[b * 2 + 1] * W2[65] + b2[0];
        out[b] = sigmoid_f(s);
    }
}

// ---------------------------------------------------------------------------
extern "C" void kernel_launch(void* const* d_in, const int* in_sizes, int n_in,
                              void* d_out, int out_size)
{
    const float* x   = (const float*)d_in[0];
    const float* a   = (const float*)d_in[1];
    const float* dv  = (const float*)d_in[2];
    const float* emb = (const float*)d_in[3];
    const float* gk  = (const float*)d_in[4];
    const float* grk = (const float*)d_in[5];
    const float* gbi = (const float*)d_in[6];
    const float* gbr = (const float*)d_in[7];
    const float* W1  = (const float*)d_in[8];
    const float* b1  = (const float*)d_in[9];
    const float* W2  = (const float*)d_in[10];
    const float* b2  = (const float*)d_in[11];
    float* out = (float*)d_out;

    cudaFuncSetAttribute(k1_gemm, cudaFuncAttributeMaxDynamicSharedMemorySize, SMEM_K1);
    cudaFuncSetAttribute(k3_gru,  cudaFuncAttributeMaxDynamicSharedMemorySize, SMEM_K3);

    k0_prep<<<NCH, 256>>>(emb);
    k1_gemm<<<GRID1, 256, SMEM_K1>>>(x, a);
    k2_reduce_proj<<<ROWS_TOT / 16, 128>>>(gk, gbi);
    k3_gru<<<B_, 384, SMEM_K3>>>(grk, gbr, dv, W1, b1, W2, b2, out);
}

// round 10
// speedup vs baseline: 2.2653x; 1.1587x over previous
#include <cuda_runtime.h>
#include <cstdint>

// ------------------------- problem dims -------------------------
#define B_ 32
#define T_ 100
#define V_ 20000
#define E_ 128
#define H_ 128
#define M_ 64
#define ROWS_X (B_*T_)          // 3200
#define ROWS_TOT (ROWS_X + B_)  // 3232

// ------------------------- k1 config ----------------------------
#define CK 64                   // k per chunk (64 fp16 = 128B rows, SW128)
#define NCH 313                 // ceil(20000/64)
#define NRT 26                  // row tiles of 128
#define NSPL 17                 // K splits
#define BASECH 18               // 313 = 7*19 + 10*18
#define EXTRA 7
#define GRID1 (NRT*NSPL)        // 442

// per-stage smem: AH 16K | AL 16K | BH 16K = 48KB; 2 stages = 96KB
#define STG_BYTES 49152
#define OFF_AH 0
#define OFF_AL 16384
#define OFF_BH 32768
#define SMEM_K1 (2*STG_BYTES)

// k3 dynamic smem layout (floats)
#define K3_XP   0                    // [100*384]
#define K3_RP   (K3_XP + T_*384)     // [384]
#define K3_H    (K3_RP + 384)        // [128]
#define K3_MSK  (K3_H + 128)         // [100]
#define K3_CS   (K3_MSK + 100)       // [64]
#define SMEM_K3 ((K3_CS + 64 + 4) * 4)   // ~156.4 KB

// ------------------------- scratch globals ----------------------
__device__ float    g_parts[(size_t)NSPL * ROWS_TOT * 128];  // 28.1 MB
__device__ uint32_t g_ebh[(size_t)NCH * 4096];               // emb fp16, tile-swizzled
__device__ float    g_P[(size_t)ROWS_X * 384];
__device__ float    g_mask[ROWS_X];
__device__ float    g_ae[B_ * E_];

// ------------------------- helpers ------------------------------
__device__ __forceinline__ unsigned su32(const void* p) {
    return (unsigned)__cvta_generic_to_shared(p);
}
__device__ __forceinline__ void cpa16(unsigned dst, const void* src) {
    asm volatile("cp.async.ca.shared.global [%0], [%1], 16;\n"
                 :: "r"(dst), "l"(src));
}
__device__ __forceinline__ void ldsm4(uint32_t* r, uint32_t addr) {
    asm volatile("ldmatrix.sync.aligned.m8n8.x4.shared.b16 {%0,%1,%2,%3}, [%4];"
                 : "=r"(r[0]), "=r"(r[1]), "=r"(r[2]), "=r"(r[3]) : "r"(addr));
}
__device__ __forceinline__ void mma16816(float* c, const uint32_t* a, const uint32_t* b) {
    asm volatile("mma.sync.aligned.m16n8k16.row.col.f32.f16.f16.f32 "
                 "{%0,%1,%2,%3}, {%4,%5,%6,%7}, {%8,%9}, {%0,%1,%2,%3};"
                 : "+f"(c[0]), "+f"(c[1]), "+f"(c[2]), "+f"(c[3])
                 : "r"(a[0]), "r"(a[1]), "r"(a[2]), "r"(a[3]), "r"(b[0]), "r"(b[1]));
}
// pack two floats -> fp16x2
__device__ __forceinline__ void cvt2h(float a, float b, uint32_t& p) {
    asm("cvt.rn.f16x2.f32 %0, %1, %2;" : "=r"(p) : "f"(b), "f"(a));
}
// unpack fp16x2 -> two floats
__device__ __forceinline__ float2 h2f(uint32_t p) {
    float lo, hi;
    asm("{\n\t.reg .f16 l, h;\n\tmov.b32 {l, h}, %2;\n\t"
        "cvt.f32.f16 %0, l;\n\tcvt.f32.f16 %1, h;\n\t}"
        : "=f"(lo), "=f"(hi) : "r"(p));
    return make_float2(lo, hi);
}

// fast transcendentals (MUFU-based, err ~2^-22)
#define LOG2E_ 1.4426950408889634f
__device__ __forceinline__ float ex2f(float x) {
    float r; asm("ex2.approx.f32 %0, %1;" : "=f"(r) : "f"(x)); return r;
}
__device__ __forceinline__ float rcpf(float x) {
    float r; asm("rcp.approx.f32 %0, %1;" : "=f"(r) : "f"(x)); return r;
}
__device__ __forceinline__ float sigmoid_f(float v) {
    return rcpf(1.f + ex2f(-v * LOG2E_));
}
__device__ __forceinline__ float tanh_f(float v) {
    return 1.f - 2.f * rcpf(ex2f(2.f * LOG2E_ * v) + 1.f);
}

// ---------------------------------------------------------------------------
// Kernel 0: emb -> transposed fp16, SW128-swizzled 16KB tiles.
// Tile c: [n=0..127 rows][k=0..63 fp16], 128B rows. One CTA per chunk.
// ---------------------------------------------------------------------------
__global__ void __launch_bounds__(256) k0_prep(const float* __restrict__ emb)
{
    __shared__ float se[64][129];   // [kl][n]
    const int c = blockIdx.x, tid = threadIdx.x;

    for (int i = tid; i < 64 * 128; i += 256) {
        int kl = i >> 7, r = i & 127;
        int k = c * CK + kl;
        se[kl][r] = (k < V_) ? emb[(size_t)k * E_ + r] : 0.f;
    }
    __syncthreads();

    uint32_t* oh = g_ebh + (size_t)c * 4096;
    for (int p = tid; p < 4096; p += 256) {
        uint32_t bo = p * 4;
        uint32_t lg = bo ^ ((bo >> 3) & 0x70);   // swizzle is an involution
        int r = lg >> 7, kl0 = (lg & 127) >> 1;
        uint32_t hw;
        cvt2h(se[kl0][r], se[kl0 + 1][r], hw);
        oh[p] = hw;
    }
}

// ---------------------------------------------------------------------------
// Kernel 1: 2-term fp16 GEMM via ldmatrix + mma.sync (HMMA), split-K partials.
// x = xh + xl (fp16 split, residual 2^-22); emb = e (fp16, 2^-11).
// 512 threads, 16 warps 4x4, warp tile 32x32, CTA tile 128x128.
// ---------------------------------------------------------------------------
__global__ void __launch_bounds__(512, 1) k1_gemm(
    const float* __restrict__ x, const float* __restrict__ a_)
{
    extern __shared__ char smem[];
    const uint32_t sb = su32(smem);
    const int tid = threadIdx.x;
    const int lane = tid & 31;
    const int wid = tid >> 5;
    const int wm = wid >> 2;
    const int wn = wid & 3;

    const int rt = blockIdx.x % NRT;
    const int sp = blockIdx.x / NRT;
    const int m0 = rt * 128;
    const int nch = BASECH + (sp < EXTRA ? 1 : 0);
    const int c0  = sp * BASECH + (sp < EXTRA ? sp : EXTRA);

    const int arow = tid >> 2;          // 0..127
    const int acol4 = tid & 3;
    const uint32_t xs_a = (uint32_t)(arow & 7) << 4;

    const float* rowp;
    {
        int m = m0 + arow;
        if (m < ROWS_X)        rowp = x  + (size_t)m * V_;
        else if (m < ROWS_TOT) rowp = a_ + (size_t)(m - ROWS_X) * V_;
        else                   rowp = nullptr;
    }

    const int aq = lane >> 3;
    const int a_row_off = (aq & 1) * 8 + (lane & 7);
    const uint32_t a_kboff = (uint32_t)(aq >> 1) * 16;
    const uint32_t abase0 = (uint32_t)(wm * 32 + 0 * 16 + a_row_off) * 128;
    const uint32_t abase1 = (uint32_t)(wm * 32 + 1 * 16 + a_row_off) * 128;
    const int bjj = lane >> 4;
    const uint32_t b_kboff = (uint32_t)((lane >> 3) & 1) * 16;
    const uint32_t bbase0 = (uint32_t)(wn * 32 + 0 * 16 + bjj * 8 + (lane & 7)) * 128;
    const uint32_t bbase1 = (uint32_t)(wn * 32 + 1 * 16 + bjj * 8 + (lane & 7)) * 128;
    const uint32_t xorv = (uint32_t)(lane & 7) << 4;

    float acc[2][4][4];
    #pragma unroll
    for (int i = 0; i < 2; i++)
        #pragma unroll
        for (int j = 0; j < 4; j++)
            #pragma unroll
            for (int q = 0; q < 4; q++) acc[i][j][q] = 0.f;

    float4 av[4];

    auto loadA = [&](int c) {
        #pragma unroll
        for (int q = 0; q < 4; q++) {
            int kb = c * CK + q * 16 + acol4 * 4;
            av[q] = (rowp && kb < V_) ? *(const float4*)(rowp + kb)
                                      : make_float4(0.f, 0.f, 0.f, 0.f);
        }
    };
    // x -> fp16 hi + residual lo, swizzled STS
    auto stsA = [&](int s) {
        const uint32_t ah = sb + s * STG_BYTES + OFF_AH + arow * 128;
        const uint32_t al = sb + s * STG_BYTES + OFF_AL + arow * 128;
        #pragma unroll
        for (int q = 0; q < 4; q++) {
            uint32_t ina = ((uint32_t)(q * 32 + acol4 * 8)) ^ xs_a;
            float4 v = av[q];
            uint32_t h0, h1, l0, l1;
            cvt2h(v.x, v.y, h0);
            cvt2h(v.z, v.w, h1);
            float2 f0 = h2f(h0), f1 = h2f(h1);
            cvt2h(v.x - f0.x, v.y - f0.y, l0);
            cvt2h(v.z - f1.x, v.w - f1.y, l1);
            asm volatile("st.shared.v2.b32 [%0], {%1,%2};" :: "r"(ah + ina), "r"(h0), "r"(h1));
            asm volatile("st.shared.v2.b32 [%0], {%1,%2};" :: "r"(al + ina), "r"(l0), "r"(l1));
        }
    };
    auto cpB = [&](int c, int s) {
        const char* srcH = (const char*)g_ebh + (size_t)c * 16384;
        const uint32_t bh = sb + s * STG_BYTES + OFF_BH;
        #pragma unroll
        for (int j = 0; j < 2; j++) {
            int off = (j * 512 + tid) * 16;
            cpa16(bh + off, srcH + off);
        }
        asm volatile("cp.async.commit_group;");
    };

    auto mmaStep = [&](int s, int ks) {
        const uint32_t ahs = sb + s * STG_BYTES + OFF_AH;
        const uint32_t als = sb + s * STG_BYTES + OFF_AL;
        const uint32_t bhs = sb + s * STG_BYTES + OFF_BH;
        const uint32_t kta = ((uint32_t)(ks * 32) + a_kboff) ^ xorv;
        const uint32_t ktb = ((uint32_t)(ks * 32) + b_kboff) ^ xorv;
        uint32_t ah0[4], ah1[4], al0[4], al1[4], bh[2][4];
        ldsm4(ah0, ahs + abase0 + kta);
        ldsm4(ah1, ahs + abase1 + kta);
        ldsm4(al0, als + abase0 + kta);
        ldsm4(al1, als + abase1 + kta);
        ldsm4(bh[0], bhs + bbase0 + ktb);
        ldsm4(bh[1], bhs + bbase1 + ktb);
        #pragma unroll
        for (int j = 0; j < 4; j++) {
            const uint32_t* bhp = &bh[j >> 1][(j & 1) * 2];
            mma16816(acc[0][j], ah0, bhp);
            mma16816(acc[0][j], al0, bhp);
            mma16816(acc[1][j], ah1, bhp);
            mma16816(acc[1][j], al1, bhp);
        }
    };

    // ---- prologue ----
    loadA(c0);
    stsA(0);
    cpB(c0, 0);
    if (nch > 1) loadA(c0 + 1);

    for (int t = 0; t < nch; t++) {
        const int s = t & 1;
        asm volatile("cp.async.wait_group 0;" ::: "memory");
        __syncthreads();   // buf s ready; all warps done reading buf s^1

        if (t + 1 < nch) {
            cpB(c0 + t + 1, s ^ 1);
            stsA(s ^ 1);
        }
        mmaStep(s, 0);
        mmaStep(s, 1);
        if (t + 2 < nch) loadA(c0 + t + 2);
        mmaStep(s, 2);
        mmaStep(s, 3);
    }

    // ---- epilogue: write this split's partial tile ----
    const int gid = lane >> 2, tig = lane & 3;
    #pragma unroll
    for (int i = 0; i < 2; i++) {
        int mrow = m0 + wm * 32 + i * 16 + gid;
        #pragma unroll
        for (int j = 0; j < 4; j++) {
            int n = wn * 32 + j * 8 + tig * 2;
            if (mrow < ROWS_TOT) {
                float* d0 = g_parts + ((size_t)sp * ROWS_TOT + mrow) * 128 + n;
                *(float2*)d0 = make_float2(acc[i][j][0], acc[i][j][1]);
            }
            if (mrow + 8 < ROWS_TOT) {
                float* d1 = g_parts + ((size_t)sp * ROWS_TOT + mrow + 8) * 128 + n;
                *(float2*)d1 = make_float2(acc[i][j][2], acc[i][j][3]);
            }
        }
    }
}

// ---------------------------------------------------------------------------
// Kernel 2: reduce partials + tanh -> xe; mask; x_proj = xe@gru_k + b_i.
// ---------------------------------------------------------------------------
__global__ void __launch_bounds__(128) k2_reduce_proj(
    const float* __restrict__ gk, const float* __restrict__ gbi)
{
    __shared__ float xs[16][128];
    __shared__ int nz[16];
    const int tid = threadIdx.x;
    const int r0 = blockIdx.x * 16;

    if (tid < 16) nz[tid] = 0;
    __syncthreads();

    for (int i = tid; i < 16 * 128; i += 128) {
        int r = i >> 7, n = i & 127;
        int m = r0 + r;
        float s = 0.f;
        const float* pp = g_parts + (size_t)m * 128 + n;
        #pragma unroll
        for (int sp = 0; sp < NSPL; sp++) s += pp[(size_t)sp * ROWS_TOT * 128];
        float v = tanh_f(s);
        xs[r][n] = v;
        if (v != 0.f) nz[r] = 1;
    }
    __syncthreads();

    if (r0 < ROWS_X) {
        float acc[16][3];
        #pragma unroll
        for (int r = 0; r < 16; r++) { acc[r][0] = 0.f; acc[r][1] = 0.f; acc[r][2] = 0.f; }
        for (int k = 0; k < 128; k++) {
            float w0 = gk[k * 384 + tid];
            float w1 = gk[k * 384 + 128 + tid];
            float w2 = gk[k * 384 + 256 + tid];
            #pragma unroll
            for (int r = 0; r < 16; r++) {
                float xv = xs[r][k];
                acc[r][0] = fmaf(xv, w0, acc[r][0]);
                acc[r][1] = fmaf(xv, w1, acc[r][1]);
                acc[r][2] = fmaf(xv, w2, acc[r][2]);
            }
        }
        float bb0 = gbi[tid], bb1 = gbi[128 + tid], bb2 = gbi[256 + tid];
        #pragma unroll
        for (int r = 0; r < 16; r++) {
            size_t m = (size_t)(r0 + r);
            g_P[m * 384 + tid]       = acc[r][0] + bb0;
            g_P[m * 384 + 128 + tid] = acc[r][1] + bb1;
            g_P[m * 384 + 256 + tid] = acc[r][2] + bb2;
        }
        if (tid < 16) g_mask[r0 + tid] = nz[tid] ? 1.f : 0.f;
    } else {
        for (int i = tid; i < 16 * 128; i += 128) {
            int r = i >> 7, n = i & 127;
            g_ae[(r0 - ROWS_X + r) * 128 + n] = xs[r][n];
        }
    }
}

// ---------------------------------------------------------------------------
// Kernel 3: per-batch GRU + head. 32 CTAs x 384 threads. x_proj + masks fully
// resident in dynamic smem; zero global traffic inside the recurrence loop.
// ---------------------------------------------------------------------------
__global__ void __launch_bounds__(384, 1) k3_gru(
    const float* __restrict__ grk, const float* __restrict__ gbr,
    const float* __restrict__ dvec, const float* __restrict__ W1,
    const float* __restrict__ b1, const float* __restrict__ W2,
    const float* __restrict__ b2, float* __restrict__ out)
{
    extern __shared__ float sm3[];
    float* xp  = sm3 + K3_XP;
    float* rp  = sm3 + K3_RP;
    float* h_s = sm3 + K3_H;
    float* msk = sm3 + K3_MSK;
    float* cs  = sm3 + K3_CS;

    const int tid = threadIdx.x;
    const int b = blockIdx.x;

    {
        const float* src = g_P + (size_t)b * T_ * 384;
        #pragma unroll
        for (int it = 0; it < 25; it++) {
            int i = it * 1536 + tid * 4;
            cpa16(su32(xp + i), src + i);
        }
        if (tid < 25) cpa16(su32(msk + tid * 4), g_mask + b * T_ + tid * 4);
        asm volatile("cp.async.commit_group;");
    }

    unsigned long long w2[64];
    #pragma unroll
    for (int q = 0; q < 64; q++) {
        float w0 = grk[(2 * q)     * 384 + tid];
        float w1 = grk[(2 * q + 1) * 384 + tid];
        asm("mov.b64 %0, {%1, %2};" : "=l"(w2[q]) : "f"(w0), "f"(w1));
    }
    const float bias = gbr[tid];

    if (tid < 128) h_s[tid] = 0.f;
    asm volatile("cp.async.wait_group 0;" ::: "memory");
    __syncthreads();

    for (int t = 0; t < T_; t++) {
        unsigned long long a0 = 0ULL, a1 = 0ULL, a2 = 0ULL, a3 = 0ULL;
        #pragma unroll
        for (int q = 0; q < 8; q++) {
            ulonglong2 u0 = *(const ulonglong2*)&h_s[q * 4];
            ulonglong2 u1 = *(const ulonglong2*)&h_s[32 + q * 4];
            ulonglong2 u2 = *(const ulonglong2*)&h_s[64 + q * 4];
            ulonglong2 u3 = *(const ulonglong2*)&h_s[96 + q * 4];
            asm("fma.rn.f32x2 %0, %1, %2, %0;" : "+l"(a0) : "l"(u0.x), "l"(w2[2 * q]));
            asm("fma.rn.f32x2 %0, %1, %2, %0;" : "+l"(a1) : "l"(u1.x), "l"(w2[16 + 2 * q]));
            asm("fma.rn.f32x2 %0, %1, %2, %0;" : "+l"(a2) : "l"(u2.x), "l"(w2[32 + 2 * q]));
            asm("fma.rn.f32x2 %0, %1, %2, %0;" : "+l"(a3) : "l"(u3.x), "l"(w2[48 + 2 * q]));
            asm("fma.rn.f32x2 %0, %1, %2, %0;" : "+l"(a0) : "l"(u0.y), "l"(w2[2 * q + 1]));
            asm("fma.rn.f32x2 %0, %1, %2, %0;" : "+l"(a1) : "l"(u1.y), "l"(w2[16 + 2 * q + 1]));
            asm("fma.rn.f32x2 %0, %1, %2, %0;" : "+l"(a2) : "l"(u2.y), "l"(w2[32 + 2 * q + 1]));
            asm("fma.rn.f32x2 %0, %1, %2, %0;" : "+l"(a3) : "l"(u3.y), "l"(w2[48 + 2 * q + 1]));
        }
        float s0, s1, s2, s3, s4, s5, s6, s7;
        asm("mov.b64 {%0, %1}, %2;" : "=f"(s0), "=f"(s1) : "l"(a0));
        asm("mov.b64 {%0, %1}, %2;" : "=f"(s2), "=f"(s3) : "l"(a1));
        asm("mov.b64 {%0, %1}, %2;" : "=f"(s4), "=f"(s5) : "l"(a2));
        asm("mov.b64 {%0, %1}, %2;" : "=f"(s6), "=f"(s7) : "l"(a3));
        rp[tid] = ((s0 + s1) + (s2 + s3)) + ((s4 + s5) + (s6 + s7)) + bias;
        __syncthreads();

        if (tid < 128) {
            const float* xpc = xp + t * 384;
            float z  = sigmoid_f(xpc[tid] + rp[tid]);
            float r  = sigmoid_f(xpc[tid + 128] + rp[tid + 128]);
            float hh = tanh_f(xpc[tid + 256] + r * rp[tid + 256]);
            float hprev = h_s[tid];
            float hn = z * hprev + (1.f - z) * hh;
            h_s[tid] = (msk[t] != 0.f) ? hn : hprev;
        }
        __syncthreads();
    }

    if (tid < 64) {
        float acc = b1[tid];
        const float* ae = g_ae + b * 128;
        #pragma unroll 4
        for (int k = 0; k < 128; k++) acc = fmaf(h_s[k], W1[k * 64 + tid], acc);
        #pragma unroll 4
        for (int k = 0; k < 128; k++) acc = fmaf(ae[k], W1[(128 + k) * 64 + tid], acc);
        cs[tid] = tanh_f(acc) * W2[tid];
    }
    __syncthreads();
    if (tid == 0) {
        float s = 0.f;
        #pragma unroll 8
        for (int i = 0; i < 64; i++) s += cs[i];
        s += dvec[b * 2] * W2[64] + dvec[b * 2 + 1] * W2[65] + b2[0];
        out[b] = sigmoid_f(s);
    }
}

// ---------------------------------------------------------------------------
extern "C" void kernel_launch(void* const* d_in, const int* in_sizes, int n_in,
                              void* d_out, int out_size)
{
    const float* x   = (const float*)d_in[0];
    const float* a   = (const float*)d_in[1];
    const float* dv  = (const float*)d_in[2];
    const float* emb = (const float*)d_in[3];
    const float* gk  = (const float*)d_in[4];
    const float* grk = (const float*)d_in[5];
    const float* gbi = (const float*)d_in[6];
    const float* gbr = (const float*)d_in[7];
    const float* W1  = (const float*)d_in[8];
    const float* b1  = (const float*)d_in[9];
    const float* W2  = (const float*)d_in[10];
    const float* b2  = (const float*)d_in[11];
    float* out = (float*)d_out;

    cudaFuncSetAttribute(k1_gemm, cudaFuncAttributeMaxDynamicSharedMemorySize, SMEM_K1);
    cudaFuncSetAttribute(k3_gru,  cudaFuncAttributeMaxDynamicSharedMemorySize, SMEM_K3);

    k0_prep<<<NCH, 256>>>(emb);
    k1_gemm<<<GRID1, 512, SMEM_K1>>>(x, a);
    k2_reduce_proj<<<ROWS_TOT / 16, 128>>>(gk, gbi);
    k3_gru<<<B_, 384, SMEM_K3>>>(grk, gbr, dv, W1, b1, W2, b2, out);
}

// round 11
// speedup vs baseline: 2.5659x; 1.1327x over previous
#include <cuda_runtime.h>
#include <cstdint>

// ------------------------- problem dims -------------------------
#define B_ 32
#define T_ 100
#define V_ 20000
#define E_ 128
#define H_ 128
#define M_ 64
#define ROWS_X (B_*T_)          // 3200
#define ROWS_TOT (ROWS_X + B_)  // 3232

// ------------------------- k1 config ----------------------------
#define CK 64                   // k per chunk (64 fp16 = 128B rows, SW128)
#define NCH 313                 // ceil(20000/64)
#define NRT 26                  // row tiles of 128
#define NSPL 17                 // K splits
#define BASECH 18               // 313 = 7*19 + 10*18
#define EXTRA 7
#define GRID1 (NRT*NSPL)        // 442

// per-stage smem: AH 16K | BH 16K = 32KB; 2 stages = 64KB
#define STG_BYTES 32768
#define OFF_AH 0
#define OFF_BH 16384
#define SMEM_K1 (2*STG_BYTES)

// k3 dynamic smem layout (floats)
#define K3_XP   0                    // [100*384]
#define K3_RP   (K3_XP + T_*384)     // [384]
#define K3_H    (K3_RP + 384)        // [128]
#define K3_MSK  (K3_H + 128)         // [100]
#define K3_CS   (K3_MSK + 100)       // [64]
#define SMEM_K3 ((K3_CS + 64 + 4) * 4)   // ~156.4 KB

// ------------------------- scratch globals ----------------------
__device__ float    g_parts[(size_t)NSPL * ROWS_TOT * 128];  // 28.1 MB
__device__ uint32_t g_ebh[(size_t)NCH * 4096];               // emb fp16, tile-swizzled
__device__ float    g_P[(size_t)ROWS_X * 384];
__device__ float    g_mask[ROWS_X];
__device__ float    g_ae[B_ * E_];

// ------------------------- helpers ------------------------------
__device__ __forceinline__ unsigned su32(const void* p) {
    return (unsigned)__cvta_generic_to_shared(p);
}
__device__ __forceinline__ void cpa16(unsigned dst, const void* src) {
    asm volatile("cp.async.ca.shared.global [%0], [%1], 16;\n"
                 :: "r"(dst), "l"(src));
}
__device__ __forceinline__ void ldsm4(uint32_t* r, uint32_t addr) {
    asm volatile("ldmatrix.sync.aligned.m8n8.x4.shared.b16 {%0,%1,%2,%3}, [%4];"
                 : "=r"(r[0]), "=r"(r[1]), "=r"(r[2]), "=r"(r[3]) : "r"(addr));
}
__device__ __forceinline__ void mma16816(float* c, const uint32_t* a, const uint32_t* b) {
    asm volatile("mma.sync.aligned.m16n8k16.row.col.f32.f16.f16.f32 "
                 "{%0,%1,%2,%3}, {%4,%5,%6,%7}, {%8,%9}, {%0,%1,%2,%3};"
                 : "+f"(c[0]), "+f"(c[1]), "+f"(c[2]), "+f"(c[3])
                 : "r"(a[0]), "r"(a[1]), "r"(a[2]), "r"(a[3]), "r"(b[0]), "r"(b[1]));
}
// pack two floats -> fp16x2
__device__ __forceinline__ void cvt2h(float a, float b, uint32_t& p) {
    asm("cvt.rn.f16x2.f32 %0, %1, %2;" : "=r"(p) : "f"(b), "f"(a));
}

// fast transcendentals (MUFU-based, err ~2^-22)
#define LOG2E_ 1.4426950408889634f
__device__ __forceinline__ float ex2f(float x) {
    float r; asm("ex2.approx.f32 %0, %1;" : "=f"(r) : "f"(x)); return r;
}
__device__ __forceinline__ float rcpf(float x) {
    float r; asm("rcp.approx.f32 %0, %1;" : "=f"(r) : "f"(x)); return r;
}
__device__ __forceinline__ float sigmoid_f(float v) {
    return rcpf(1.f + ex2f(-v * LOG2E_));
}
__device__ __forceinline__ float tanh_f(float v) {
    return 1.f - 2.f * rcpf(ex2f(2.f * LOG2E_ * v) + 1.f);
}

// ---------------------------------------------------------------------------
// Kernel 0: emb -> transposed fp16, SW128-swizzled 16KB tiles.
// Tile c: [n=0..127 rows][k=0..63 fp16], 128B rows. One CTA per chunk.
// ---------------------------------------------------------------------------
__global__ void __launch_bounds__(256) k0_prep(const float* __restrict__ emb)
{
    __shared__ float se[64][129];   // [kl][n]
    const int c = blockIdx.x, tid = threadIdx.x;

    for (int i = tid; i < 64 * 128; i += 256) {
        int kl = i >> 7, r = i & 127;
        int k = c * CK + kl;
        se[kl][r] = (k < V_) ? emb[(size_t)k * E_ + r] : 0.f;
    }
    __syncthreads();

    uint32_t* oh = g_ebh + (size_t)c * 4096;
    for (int p = tid; p < 4096; p += 256) {
        uint32_t bo = p * 4;
        uint32_t lg = bo ^ ((bo >> 3) & 0x70);   // swizzle is an involution
        int r = lg >> 7, kl0 = (lg & 127) >> 1;
        uint32_t hw;
        cvt2h(se[kl0][r], se[kl0 + 1][r], hw);
        oh[p] = hw;
    }
}

// ---------------------------------------------------------------------------
// Kernel 1: 1-term fp16 GEMM via ldmatrix + mma.sync (HMMA), split-K partials.
// x -> fp16 (2^-12 rounding), emb -> fp16; single product per k.
// 512 threads, 16 warps 4x4, warp tile 32x32, CTA tile 128x128.
// ---------------------------------------------------------------------------
__global__ void __launch_bounds__(512, 1) k1_gemm(
    const float* __restrict__ x, const float* __restrict__ a_)
{
    extern __shared__ char smem[];
    const uint32_t sb = su32(smem);
    const int tid = threadIdx.x;
    const int lane = tid & 31;
    const int wid = tid >> 5;
    const int wm = wid >> 2;
    const int wn = wid & 3;

    const int rt = blockIdx.x % NRT;
    const int sp = blockIdx.x / NRT;
    const int m0 = rt * 128;
    const int nch = BASECH + (sp < EXTRA ? 1 : 0);
    const int c0  = sp * BASECH + (sp < EXTRA ? sp : EXTRA);

    const int arow = tid >> 2;          // 0..127
    const int acol4 = tid & 3;
    const uint32_t xs_a = (uint32_t)(arow & 7) << 4;

    const float* rowp;
    {
        int m = m0 + arow;
        if (m < ROWS_X)        rowp = x  + (size_t)m * V_;
        else if (m < ROWS_TOT) rowp = a_ + (size_t)(m - ROWS_X) * V_;
        else                   rowp = nullptr;
    }

    const int aq = lane >> 3;
    const int a_row_off = (aq & 1) * 8 + (lane & 7);
    const uint32_t a_kboff = (uint32_t)(aq >> 1) * 16;
    const uint32_t abase0 = (uint32_t)(wm * 32 + 0 * 16 + a_row_off) * 128;
    const uint32_t abase1 = (uint32_t)(wm * 32 + 1 * 16 + a_row_off) * 128;
    const int bjj = lane >> 4;
    const uint32_t b_kboff = (uint32_t)((lane >> 3) & 1) * 16;
    const uint32_t bbase0 = (uint32_t)(wn * 32 + 0 * 16 + bjj * 8 + (lane & 7)) * 128;
    const uint32_t bbase1 = (uint32_t)(wn * 32 + 1 * 16 + bjj * 8 + (lane & 7)) * 128;
    const uint32_t xorv = (uint32_t)(lane & 7) << 4;

    float acc[2][4][4];
    #pragma unroll
    for (int i = 0; i < 2; i++)
        #pragma unroll
        for (int j = 0; j < 4; j++)
            #pragma unroll
            for (int q = 0; q < 4; q++) acc[i][j][q] = 0.f;

    float4 av[4];

    auto loadA = [&](int c) {
        #pragma unroll
        for (int q = 0; q < 4; q++) {
            int kb = c * CK + q * 16 + acol4 * 4;
            av[q] = (rowp && kb < V_) ? *(const float4*)(rowp + kb)
                                      : make_float4(0.f, 0.f, 0.f, 0.f);
        }
    };
    // x -> fp16, swizzled STS
    auto stsA = [&](int s) {
        const uint32_t ah = sb + s * STG_BYTES + OFF_AH + arow * 128;
        #pragma unroll
        for (int q = 0; q < 4; q++) {
            uint32_t ina = ((uint32_t)(q * 32 + acol4 * 8)) ^ xs_a;
            float4 v = av[q];
            uint32_t h0, h1;
            cvt2h(v.x, v.y, h0);
            cvt2h(v.z, v.w, h1);
            asm volatile("st.shared.v2.b32 [%0], {%1,%2};" :: "r"(ah + ina), "r"(h0), "r"(h1));
        }
    };
    auto cpB = [&](int c, int s) {
        const char* srcH = (const char*)g_ebh + (size_t)c * 16384;
        const uint32_t bh = sb + s * STG_BYTES + OFF_BH;
        #pragma unroll
        for (int j = 0; j < 2; j++) {
            int off = (j * 512 + tid) * 16;
            cpa16(bh + off, srcH + off);
        }
        asm volatile("cp.async.commit_group;");
    };

    auto mmaStep = [&](int s, int ks) {
        const uint32_t ahs = sb + s * STG_BYTES + OFF_AH;
        const uint32_t bhs = sb + s * STG_BYTES + OFF_BH;
        const uint32_t kta = ((uint32_t)(ks * 32) + a_kboff) ^ xorv;
        const uint32_t ktb = ((uint32_t)(ks * 32) + b_kboff) ^ xorv;
        uint32_t ah0[4], ah1[4], bh[2][4];
        ldsm4(ah0, ahs + abase0 + kta);
        ldsm4(ah1, ahs + abase1 + kta);
        ldsm4(bh[0], bhs + bbase0 + ktb);
        ldsm4(bh[1], bhs + bbase1 + ktb);
        #pragma unroll
        for (int j = 0; j < 4; j++) {
            const uint32_t* bhp = &bh[j >> 1][(j & 1) * 2];
            mma16816(acc[0][j], ah0, bhp);
            mma16816(acc[1][j], ah1, bhp);
        }
    };

    // ---- prologue ----
    loadA(c0);
    stsA(0);
    cpB(c0, 0);
    if (nch > 1) loadA(c0 + 1);

    for (int t = 0; t < nch; t++) {
        const int s = t & 1;
        asm volatile("cp.async.wait_group 0;" ::: "memory");
        __syncthreads();   // buf s ready; all warps done reading buf s^1

        if (t + 1 < nch) {
            cpB(c0 + t + 1, s ^ 1);
            stsA(s ^ 1);
        }
        mmaStep(s, 0);
        mmaStep(s, 1);
        if (t + 2 < nch) loadA(c0 + t + 2);
        mmaStep(s, 2);
        mmaStep(s, 3);
    }

    // ---- epilogue: write this split's partial tile ----
    const int gid = lane >> 2, tig = lane & 3;
    #pragma unroll
    for (int i = 0; i < 2; i++) {
        int mrow = m0 + wm * 32 + i * 16 + gid;
        #pragma unroll
        for (int j = 0; j < 4; j++) {
            int n = wn * 32 + j * 8 + tig * 2;
            if (mrow < ROWS_TOT) {
                float* d0 = g_parts + ((size_t)sp * ROWS_TOT + mrow) * 128 + n;
                *(float2*)d0 = make_float2(acc[i][j][0], acc[i][j][1]);
            }
            if (mrow + 8 < ROWS_TOT) {
                float* d1 = g_parts + ((size_t)sp * ROWS_TOT + mrow + 8) * 128 + n;
                *(float2*)d1 = make_float2(acc[i][j][2], acc[i][j][3]);
            }
        }
    }
}

// ---------------------------------------------------------------------------
// Kernel 2: reduce partials + tanh -> xe; mask; x_proj = xe@gru_k + b_i.
// ---------------------------------------------------------------------------
__global__ void __launch_bounds__(128) k2_reduce_proj(
    const float* __restrict__ gk, const float* __restrict__ gbi)
{
    __shared__ float xs[16][128];
    __shared__ int nz[16];
    const int tid = threadIdx.x;
    const int r0 = blockIdx.x * 16;

    if (tid < 16) nz[tid] = 0;
    __syncthreads();

    for (int i = tid; i < 16 * 128; i += 128) {
        int r = i >> 7, n = i & 127;
        int m = r0 + r;
        float s = 0.f;
        const float* pp = g_parts + (size_t)m * 128 + n;
        #pragma unroll
        for (int sp = 0; sp < NSPL; sp++) s += pp[(size_t)sp * ROWS_TOT * 128];
        float v = tanh_f(s);
        xs[r][n] = v;
        if (v != 0.f) nz[r] = 1;
    }
    __syncthreads();

    if (r0 < ROWS_X) {
        float acc[16][3];
        #pragma unroll
        for (int r = 0; r < 16; r++) { acc[r][0] = 0.f; acc[r][1] = 0.f; acc[r][2] = 0.f; }
        for (int k = 0; k < 128; k++) {
            float w0 = gk[k * 384 + tid];
            float w1 = gk[k * 384 + 128 + tid];
            float w2 = gk[k * 384 + 256 + tid];
            #pragma unroll
            for (int r = 0; r < 16; r++) {
                float xv = xs[r][k];
                acc[r][0] = fmaf(xv, w0, acc[r][0]);
                acc[r][1] = fmaf(xv, w1, acc[r][1]);
                acc[r][2] = fmaf(xv, w2, acc[r][2]);
            }
        }
        float bb0 = gbi[tid], bb1 = gbi[128 + tid], bb2 = gbi[256 + tid];
        #pragma unroll
        for (int r = 0; r < 16; r++) {
            size_t m = (size_t)(r0 + r);
            g_P[m * 384 + tid]       = acc[r][0] + bb0;
            g_P[m * 384 + 128 + tid] = acc[r][1] + bb1;
            g_P[m * 384 + 256 + tid] = acc[r][2] + bb2;
        }
        if (tid < 16) g_mask[r0 + tid] = nz[tid] ? 1.f : 0.f;
    } else {
        for (int i = tid; i < 16 * 128; i += 128) {
            int r = i >> 7, n = i & 127;
            g_ae[(r0 - ROWS_X + r) * 128 + n] = xs[r][n];
        }
    }
}

// ---------------------------------------------------------------------------
// Kernel 3: per-batch GRU + head. 32 CTAs x 384 threads. x_proj + masks fully
// resident in dynamic smem; zero global traffic inside the recurrence loop.
// ---------------------------------------------------------------------------
__global__ void __launch_bounds__(384, 1) k3_gru(
    const float* __restrict__ grk, const float* __restrict__ gbr,
    const float* __restrict__ dvec, const float* __restrict__ W1,
    const float* __restrict__ b1, const float* __restrict__ W2,
    const float* __restrict__ b2, float* __restrict__ out)
{
    extern __shared__ float sm3[];
    float* xp  = sm3 + K3_XP;
    float* rp  = sm3 + K3_RP;
    float* h_s = sm3 + K3_H;
    float* msk = sm3 + K3_MSK;
    float* cs  = sm3 + K3_CS;

    const int tid = threadIdx.x;
    const int b = blockIdx.x;

    {
        const float* src = g_P + (size_t)b * T_ * 384;
        #pragma unroll
        for (int it = 0; it < 25; it++) {
            int i = it * 1536 + tid * 4;
            cpa16(su32(xp + i), src + i);
        }
        if (tid < 25) cpa16(su32(msk + tid * 4), g_mask + b * T_ + tid * 4);
        asm volatile("cp.async.commit_group;");
    }

    unsigned long long w2[64];
    #pragma unroll
    for (int q = 0; q < 64; q++) {
        float w0 = grk[(2 * q)     * 384 + tid];
        float w1 = grk[(2 * q + 1) * 384 + tid];
        asm("mov.b64 %0, {%1, %2};" : "=l"(w2[q]) : "f"(w0), "f"(w1));
    }
    const float bias = gbr[tid];

    if (tid < 128) h_s[tid] = 0.f;
    asm volatile("cp.async.wait_group 0;" ::: "memory");
    __syncthreads();

    for (int t = 0; t < T_; t++) {
        unsigned long long a0 = 0ULL, a1 = 0ULL, a2 = 0ULL, a3 = 0ULL;
        #pragma unroll
        for (int q = 0; q < 8; q++) {
            ulonglong2 u0 = *(const ulonglong2*)&h_s[q * 4];
            ulonglong2 u1 = *(const ulonglong2*)&h_s[32 + q * 4];
            ulonglong2 u2 = *(const ulonglong2*)&h_s[64 + q * 4];
            ulonglong2 u3 = *(const ulonglong2*)&h_s[96 + q * 4];
            asm("fma.rn.f32x2 %0, %1, %2, %0;" : "+l"(a0) : "l"(u0.x), "l"(w2[2 * q]));
            asm("fma.rn.f32x2 %0, %1, %2, %0;" : "+l"(a1) : "l"(u1.x), "l"(w2[16 + 2 * q]));
            asm("fma.rn.f32x2 %0, %1, %2, %0;" : "+l"(a2) : "l"(u2.x), "l"(w2[32 + 2 * q]));
            asm("fma.rn.f32x2 %0, %1, %2, %0;" : "+l"(a3) : "l"(u3.x), "l"(w2[48 + 2 * q]));
            asm("fma.rn.f32x2 %0, %1, %2, %0;" : "+l"(a0) : "l"(u0.y), "l"(w2[2 * q + 1]));
            asm("fma.rn.f32x2 %0, %1, %2, %0;" : "+l"(a1) : "l"(u1.y), "l"(w2[16 + 2 * q + 1]));
            asm("fma.rn.f32x2 %0, %1, %2, %0;" : "+l"(a2) : "l"(u2.y), "l"(w2[32 + 2 * q + 1]));
            asm("fma.rn.f32x2 %0, %1, %2, %0;" : "+l"(a3) : "l"(u3.y), "l"(w2[48 + 2 * q + 1]));
        }
        float s0, s1, s2, s3, s4, s5, s6, s7;
        asm("mov.b64 {%0, %1}, %2;" : "=f"(s0), "=f"(s1) : "l"(a0));
        asm("mov.b64 {%0, %1}, %2;" : "=f"(s2), "=f"(s3) : "l"(a1));
        asm("mov.b64 {%0, %1}, %2;" : "=f"(s4), "=f"(s5) : "l"(a2));
        asm("mov.b64 {%0, %1}, %2;" : "=f"(s6), "=f"(s7) : "l"(a3));
        rp[tid] = ((s0 + s1) + (s2 + s3)) + ((s4 + s5) + (s6 + s7)) + bias;
        __syncthreads();

        if (tid < 128) {
            const float* xpc = xp + t * 384;
            float z  = sigmoid_f(xpc[tid] + rp[tid]);
            float r  = sigmoid_f(xpc[tid + 128] + rp[tid + 128]);
            float hh = tanh_f(xpc[tid + 256] + r * rp[tid + 256]);
            float hprev = h_s[tid];
            float hn = z * hprev + (1.f - z) * hh;
            h_s[tid] = (msk[t] != 0.f) ? hn : hprev;
        }
        __syncthreads();
    }

    if (tid < 64) {
        float acc = b1[tid];
        const float* ae = g_ae + b * 128;
        #pragma unroll 4
        for (int k = 0; k < 128; k++) acc = fmaf(h_s[k], W1[k * 64 + tid], acc);
        #pragma unroll 4
        for (int k = 0; k < 128; k++) acc = fmaf(ae[k], W1[(128 + k) * 64 + tid], acc);
        cs[tid] = tanh_f(acc) * W2[tid];
    }
    __syncthreads();
    if (tid == 0) {
        float s = 0.f;
        #pragma unroll 8
        for (int i = 0; i < 64; i++) s += cs[i];
        s += dvec[b * 2] * W2[64] + dvec[b * 2 + 1] * W2[65] + b2[0];
        out[b] = sigmoid_f(s);
    }
}

// ---------------------------------------------------------------------------
extern "C" void kernel_launch(void* const* d_in, const int* in_sizes, int n_in,
                              void* d_out, int out_size)
{
    const float* x   = (const float*)d_in[0];
    const float* a   = (const float*)d_in[1];
    const float* dv  = (const float*)d_in[2];
    const float* emb = (const float*)d_in[3];
    const float* gk  = (const float*)d_in[4];
    const float* grk = (const float*)d_in[5];
    const float* gbi = (const float*)d_in[6];
    const float* gbr = (const float*)d_in[7];
    const float* W1  = (const float*)d_in[8];
    const float* b1  = (const float*)d_in[9];
    const float* W2  = (const float*)d_in[10];
    const float* b2  = (const float*)d_in[11];
    float* out = (float*)d_out;

    cudaFuncSetAttribute(k1_gemm, cudaFuncAttributeMaxDynamicSharedMemorySize, SMEM_K1);
    cudaFuncSetAttribute(k3_gru,  cudaFuncAttributeMaxDynamicSharedMemorySize, SMEM_K3);

    k0_prep<<<NCH, 256>>>(emb);
    k1_gemm<<<GRID1, 512, SMEM_K1>>>(x, a);
    k2_reduce_proj<<<ROWS_TOT / 16, 128>>>(gk, gbi);
    k3_gru<<<B_, 384, SMEM_K3>>>(grk, gbr, dv, W1, b1, W2, b2, out);
}